// round 1
// baseline (speedup 1.0000x reference)
#include <cuda_runtime.h>
#include <cstdint>

#define DIM     1024
#define NHEADS  16
#define HDIM    64
#define SEQ     2048
#define BATCH   4
#define NTOK    (BATCH * SEQ)          // 8192
#define SCALE   0.125f                 // 1/sqrt(64)

// -------- scratch (device globals: allocation-free) --------
__device__ float g_q[(size_t)BATCH * NHEADS * SEQ * HDIM];     // [B,H,S,D]
__device__ float g_k[(size_t)BATCH * NHEADS * SEQ * HDIM];
__device__ float g_v[(size_t)BATCH * NHEADS * SEQ * HDIM];
__device__ float g_attn[(size_t)NTOK * DIM];                   // [B,S,C]

// ============================================================
// SGEMM core: 128x128 tile, K-step 8, 256 threads, 8x8 microtile
// ============================================================
__device__ __forceinline__ void sgemm_core(
    const float* __restrict__ A, const float* __restrict__ B,
    int lda, int ldb, int K,
    float acc[8][8], float* As, float* Bs)
{
    const int tid = threadIdx.x;
    const int ty  = tid >> 4;        // 0..15
    const int tx  = tid & 15;        // 0..15
    const int by  = blockIdx.y;
    const int bx  = blockIdx.x;

    #pragma unroll
    for (int r = 0; r < 8; r++)
        #pragma unroll
        for (int c = 0; c < 8; c++)
            acc[r][c] = 0.f;

    const int arow = tid >> 1;             // 0..127
    const int acol = (tid & 1) * 4;        // 0 or 4
    const int brow = tid >> 5;             // 0..7
    const int bcol = (tid & 31) * 4;       // 0..124

    const float* Aptr = A + (size_t)(by * 128 + arow) * lda + acol;
    const float* Bptr = B + (size_t)brow * ldb + bx * 128 + bcol;

    for (int k0 = 0; k0 < K; k0 += 8) {
        float4 av = *(const float4*)(Aptr + k0);
        float4 bv = *(const float4*)(Bptr + (size_t)k0 * ldb);

        As[(acol + 0) * 128 + arow] = av.x;
        As[(acol + 1) * 128 + arow] = av.y;
        As[(acol + 2) * 128 + arow] = av.z;
        As[(acol + 3) * 128 + arow] = av.w;
        *(float4*)&Bs[brow * 128 + bcol] = bv;
        __syncthreads();

        #pragma unroll
        for (int kk = 0; kk < 8; kk++) {
            float a[8], b[8];
            *(float4*)(a)     = *(const float4*)&As[kk * 128 + ty * 8];
            *(float4*)(a + 4) = *(const float4*)&As[kk * 128 + ty * 8 + 4];
            *(float4*)(b)     = *(const float4*)&Bs[kk * 128 + tx * 8];
            *(float4*)(b + 4) = *(const float4*)&Bs[kk * 128 + tx * 8 + 4];
            #pragma unroll
            for (int r = 0; r < 8; r++)
                #pragma unroll
                for (int c = 0; c < 8; c++)
                    acc[r][c] = fmaf(a[r], b[c], acc[r][c]);
        }
        __syncthreads();
    }
}

// ============================================================
// Kernel 1: qkv = x @ w_qkv  -> scatter into g_q/g_k/g_v [B,H,S,D]
// ============================================================
__global__ void qkv_gemm_kernel(const float* __restrict__ x,
                                const float* __restrict__ w)
{
    __shared__ float As[8 * 128];
    __shared__ float Bs[8 * 128];
    float acc[8][8];
    sgemm_core(x, w, DIM, 3 * DIM, DIM, acc, As, Bs);

    const int tid = threadIdx.x;
    const int ty  = tid >> 4, tx = tid & 15;
    const int m0 = blockIdx.y * 128 + ty * 8;
    const int n0 = blockIdx.x * 128 + tx * 8;

    #pragma unroll
    for (int r = 0; r < 8; r++) {
        const int m = m0 + r;
        const int b = m >> 11;          // /2048
        const int s = m & 2047;
        #pragma unroll
        for (int c = 0; c < 8; c++) {
            const int n = n0 + c;
            const int three = n >> 10;
            const int h = (n >> 6) & 15;
            const int d = n & 63;
            const size_t idx = (((size_t)(b * NHEADS + h)) * SEQ + s) * HDIM + d;
            float* dst = (three == 0) ? g_q : (three == 1) ? g_k : g_v;
            dst[idx] = acc[r][c];
        }
    }
}

// ============================================================
// Kernel 2: causal flash attention, 64x64 tiles, fp32
// grid: (S/64, H, B), 256 threads
// ============================================================
__global__ void attn_kernel()
{
    extern __shared__ float sm[];
    float* Qs  = sm;              // transposed: Qs[d*64 + i]
    float* Ks  = Qs + 4096;       // transposed: Ks[d*64 + j]
    float* Vs  = Ks + 4096;       // Vs[kk*64 + d]
    float* Ss  = Vs + 4096;       // Ss[i*64 + kk]
    float* red  = Ss + 4096;      // [64*16] partial max
    float* red2 = red + 1024;     // [64*16] partial sum
    float* m_s  = red2 + 1024;    // [64]
    float* l_s  = m_s + 64;       // [64]

    const int tid = threadIdx.x;
    const int ty  = tid >> 4;     // 0..15 -> rows 4*ty..+3
    const int tx  = tid & 15;     // 0..15 -> cols 4*tx..+3
    const int qt  = blockIdx.x;
    const int h   = blockIdx.y;
    const int b   = blockIdx.z;
    const size_t base = ((size_t)(b * NHEADS + h)) * SEQ * HDIM;
    const int q0 = qt * 64;

    // load Q tile transposed
    for (int idx = tid; idx < 64 * 16; idx += 256) {
        const int row = idx >> 4;
        const int d4  = (idx & 15) << 2;
        float4 v = *(const float4*)&g_q[base + (size_t)(q0 + row) * HDIM + d4];
        Qs[(d4 + 0) * 64 + row] = v.x;
        Qs[(d4 + 1) * 64 + row] = v.y;
        Qs[(d4 + 2) * 64 + row] = v.z;
        Qs[(d4 + 3) * 64 + row] = v.w;
    }
    if (tid < 64) { m_s[tid] = -1e30f; l_s[tid] = 0.f; }

    float o[4][4] = {};

    for (int kt = 0; kt <= qt; kt++) {
        const int k0 = kt * 64;
        // Previous iteration's smem reads complete before overwriting K/V? The
        // trailing __syncthreads at loop end guarantees it; for kt==0 we also
        // need Q/m_s visible -> this sync covers both.
        __syncthreads();
        // load K (transposed) + V tiles
        for (int idx = tid; idx < 64 * 16; idx += 256) {
            const int row = idx >> 4;
            const int d4  = (idx & 15) << 2;
            float4 kv = *(const float4*)&g_k[base + (size_t)(k0 + row) * HDIM + d4];
            Ks[(d4 + 0) * 64 + row] = kv.x;
            Ks[(d4 + 1) * 64 + row] = kv.y;
            Ks[(d4 + 2) * 64 + row] = kv.z;
            Ks[(d4 + 3) * 64 + row] = kv.w;
            float4 vv = *(const float4*)&g_v[base + (size_t)(k0 + row) * HDIM + d4];
            *(float4*)&Vs[row * 64 + d4] = vv;
        }
        __syncthreads();

        // S = Q K^T (4x4 per thread)
        float s[4][4] = {};
        #pragma unroll 4
        for (int d = 0; d < 64; d++) {
            float4 qv = *(const float4*)&Qs[d * 64 + 4 * ty];
            float4 kv = *(const float4*)&Ks[d * 64 + 4 * tx];
            const float qa[4] = {qv.x, qv.y, qv.z, qv.w};
            const float ka[4] = {kv.x, kv.y, kv.z, kv.w};
            #pragma unroll
            for (int r = 0; r < 4; r++)
                #pragma unroll
                for (int c = 0; c < 4; c++)
                    s[r][c] = fmaf(qa[r], ka[c], s[r][c]);
        }

        // scale + causal mask + partial row max
        const bool diag = (kt == qt);
        float rmax[4];
        #pragma unroll
        for (int r = 0; r < 4; r++) {
            rmax[r] = -1e30f;
            const int row_g = q0 + 4 * ty + r;
            #pragma unroll
            for (int c = 0; c < 4; c++) {
                s[r][c] *= SCALE;
                if (diag && (k0 + 4 * tx + c) > row_g) s[r][c] = -1e30f;
                rmax[r] = fmaxf(rmax[r], s[r][c]);
            }
            red[(4 * ty + r) * 16 + tx] = rmax[r];
        }
        __syncthreads();

        // finish row max, compute p = exp(s - m_new), partial row sums,
        // rescale O; all reads of m_s (old) happen before the next barrier.
        float alpha[4], mnew[4];
        #pragma unroll
        for (int r = 0; r < 4; r++) {
            const int i = 4 * ty + r;
            float mt = red[i * 16];
            #pragma unroll
            for (int t = 1; t < 16; t++) mt = fmaxf(mt, red[i * 16 + t]);
            const float mo = m_s[i];
            mnew[r]  = fmaxf(mo, mt);
            alpha[r] = __expf(mo - mnew[r]);

            float4 p;
            p.x = __expf(s[r][0] - mnew[r]);
            p.y = __expf(s[r][1] - mnew[r]);
            p.z = __expf(s[r][2] - mnew[r]);
            p.w = __expf(s[r][3] - mnew[r]);
            *(float4*)&Ss[i * 64 + 4 * tx] = p;
            red2[i * 16 + tx] = p.x + p.y + p.z + p.w;

            #pragma unroll
            for (int c = 0; c < 4; c++) o[r][c] *= alpha[r];
        }
        __syncthreads();

        // one thread per row updates running stats
        if (tx == 0) {
            #pragma unroll
            for (int r = 0; r < 4; r++) {
                const int i = 4 * ty + r;
                float sum = 0.f;
                #pragma unroll
                for (int t = 0; t < 16; t++) sum += red2[i * 16 + t];
                l_s[i] = l_s[i] * alpha[r] + sum;
                m_s[i] = mnew[r];
            }
        }

        // O += P @ V
        #pragma unroll 4
        for (int kk = 0; kk < 64; kk++) {
            float4 vv = *(const float4*)&Vs[kk * 64 + 4 * tx];
            #pragma unroll
            for (int r = 0; r < 4; r++) {
                const float p = Ss[(4 * ty + r) * 64 + kk];
                o[r][0] = fmaf(p, vv.x, o[r][0]);
                o[r][1] = fmaf(p, vv.y, o[r][1]);
                o[r][2] = fmaf(p, vv.z, o[r][2]);
                o[r][3] = fmaf(p, vv.w, o[r][3]);
            }
        }
    }
    __syncthreads();   // make final l_s writes visible

    // normalize + store to g_attn [B,S,C] (C index = h*64 + d)
    #pragma unroll
    for (int r = 0; r < 4; r++) {
        const int i = 4 * ty + r;
        const float inv = 1.f / l_s[i];
        const size_t off = ((size_t)(b * SEQ + q0 + i)) * DIM + h * HDIM + 4 * tx;
        float4 ov;
        ov.x = o[r][0] * inv;
        ov.y = o[r][1] * inv;
        ov.z = o[r][2] * inv;
        ov.w = o[r][3] * inv;
        *(float4*)&g_attn[off] = ov;
    }
}

// ============================================================
// Kernel 3: out = g_attn @ w_proj + b_proj
// ============================================================
__global__ void proj_gemm_kernel(const float* __restrict__ wp,
                                 const float* __restrict__ bias,
                                 float* __restrict__ out)
{
    __shared__ float As[8 * 128];
    __shared__ float Bs[8 * 128];
    float acc[8][8];
    sgemm_core(g_attn, wp, DIM, DIM, DIM, acc, As, Bs);

    const int tid = threadIdx.x;
    const int ty  = tid >> 4, tx = tid & 15;
    const int m0 = blockIdx.y * 128 + ty * 8;
    const int n0 = blockIdx.x * 128 + tx * 8;

    #pragma unroll
    for (int r = 0; r < 8; r++) {
        #pragma unroll
        for (int c = 0; c < 8; c++) {
            const int n = n0 + c;
            out[(size_t)(m0 + r) * DIM + n] = acc[r][c] + bias[n];
        }
    }
}

// ============================================================
extern "C" void kernel_launch(void* const* d_in, const int* in_sizes, int n_in,
                              void* d_out, int out_size)
{
    const float* x      = (const float*)d_in[0];
    const float* w_qkv  = (const float*)d_in[1];
    const float* w_proj = (const float*)d_in[2];
    const float* b_proj = (const float*)d_in[3];
    float* out = (float*)d_out;

    // QKV GEMM: M=8192, N=3072
    {
        dim3 grid(3 * DIM / 128, NTOK / 128);
        qkv_gemm_kernel<<<grid, 256>>>(x, w_qkv);
    }

    // attention
    {
        const int smem_bytes = (4 * 4096 + 2 * 1024 + 128) * (int)sizeof(float); // 74240
        cudaFuncSetAttribute(attn_kernel,
                             cudaFuncAttributeMaxDynamicSharedMemorySize,
                             smem_bytes);
        dim3 grid(SEQ / 64, NHEADS, BATCH);
        attn_kernel<<<grid, 256, smem_bytes>>>();
    }

    // projection GEMM: M=8192, N=1024
    {
        dim3 grid(DIM / 128, NTOK / 128);
        proj_gemm_kernel<<<grid, 256>>>(w_proj, b_proj, out);
    }
}

// round 3
// speedup vs baseline: 1.5038x; 1.5038x over previous
#include <cuda_runtime.h>
#include <cuda_bf16.h>
#include <cstdint>

#define DIM     1024
#define NHEADS  16
#define HDIM    64
#define SEQ     2048
#define BATCH   4
#define NTOK    (BATCH * SEQ)          // 8192
#define SCALE   0.125f                 // 1/sqrt(64)

// -------- scratch (device globals: allocation-free) --------
__device__ float g_q[(size_t)BATCH * NHEADS * SEQ * HDIM];     // [B,H,S,D] fp32
__device__ float g_k[(size_t)BATCH * NHEADS * SEQ * HDIM];
__device__ float g_v[(size_t)BATCH * NHEADS * SEQ * HDIM];
__device__ __nv_bfloat16 g_xh[(size_t)NTOK * DIM];             // x hi/lo
__device__ __nv_bfloat16 g_xl[(size_t)NTOK * DIM];
__device__ __nv_bfloat16 g_wqh[(size_t)3 * DIM * DIM];         // w_qkv^T [n][k]
__device__ __nv_bfloat16 g_wql[(size_t)3 * DIM * DIM];
__device__ __nv_bfloat16 g_wph[(size_t)DIM * DIM];             // w_proj^T [n][k]
__device__ __nv_bfloat16 g_wpl[(size_t)DIM * DIM];
__device__ __nv_bfloat16 g_ah[(size_t)NTOK * DIM];             // attn out hi/lo
__device__ __nv_bfloat16 g_al[(size_t)NTOK * DIM];

// ============================================================
// helpers
// ============================================================
__device__ __forceinline__ uint32_t smem_to_u32(const void* p) {
    uint32_t a;
    asm("{ .reg .u64 t; cvta.to.shared.u64 t, %1; cvt.u32.u64 %0, t; }"
        : "=r"(a) : "l"(p));
    return a;
}

__device__ __forceinline__ void bf16split(float v, unsigned short& h, unsigned short& l) {
    __nv_bfloat16 hb = __float2bfloat16(v);
    h = __bfloat16_as_ushort(hb);
    l = __bfloat16_as_ushort(__float2bfloat16(v - __bfloat162float(hb)));
}

__device__ __forceinline__ void ldsm4(uint32_t r[4], uint32_t addr) {
    asm volatile("ldmatrix.sync.aligned.m8n8.x4.shared.b16 {%0,%1,%2,%3}, [%4];"
        : "=r"(r[0]), "=r"(r[1]), "=r"(r[2]), "=r"(r[3]) : "r"(addr));
}

__device__ __forceinline__ void mma_bf16(float d[4], const uint32_t a[4],
                                         uint32_t b0, uint32_t b1) {
    asm volatile(
        "mma.sync.aligned.m16n8k16.row.col.f32.bf16.bf16.f32 "
        "{%0,%1,%2,%3}, {%4,%5,%6,%7}, {%8,%9}, {%0,%1,%2,%3};"
        : "+f"(d[0]), "+f"(d[1]), "+f"(d[2]), "+f"(d[3])
        : "r"(a[0]), "r"(a[1]), "r"(a[2]), "r"(a[3]), "r"(b0), "r"(b1));
}

// ============================================================
// Preprocess kernels
// ============================================================
__global__ void convert_split_kernel(const float* __restrict__ in,
                                     __nv_bfloat16* __restrict__ hi,
                                     __nv_bfloat16* __restrict__ lo, int n4)
{
    const int i = blockIdx.x * blockDim.x + threadIdx.x;
    if (i >= n4) return;
    float4 v = ((const float4*)in)[i];
    unsigned short h[4], l[4];
    bf16split(v.x, h[0], l[0]); bf16split(v.y, h[1], l[1]);
    bf16split(v.z, h[2], l[2]); bf16split(v.w, h[3], l[3]);
    ((uint2*)hi)[i] = make_uint2((uint32_t)h[0] | ((uint32_t)h[1] << 16),
                                 (uint32_t)h[2] | ((uint32_t)h[3] << 16));
    ((uint2*)lo)[i] = make_uint2((uint32_t)l[0] | ((uint32_t)l[1] << 16),
                                 (uint32_t)l[2] | ((uint32_t)l[3] << 16));
}

// in [K][N] fp32 -> out hi/lo [N][K] bf16
__global__ void transpose_split_kernel(const float* __restrict__ in,
                                       __nv_bfloat16* __restrict__ hiT,
                                       __nv_bfloat16* __restrict__ loT,
                                       int K, int N)
{
    __shared__ float t[32][33];
    const int tx = threadIdx.x, ty = threadIdx.y;
    const int k0 = blockIdx.y * 32, n0 = blockIdx.x * 32;
    #pragma unroll
    for (int j = 0; j < 4; j++)
        t[ty + j * 8][tx] = in[(size_t)(k0 + ty + j * 8) * N + n0 + tx];
    __syncthreads();
    #pragma unroll
    for (int j = 0; j < 4; j++) {
        const int nn = n0 + ty + j * 8;
        const int kk = k0 + tx;
        unsigned short h, l;
        bf16split(t[tx][ty + j * 8], h, l);
        hiT[(size_t)nn * K + kk] = __ushort_as_bfloat16(h);
        loT[(size_t)nn * K + kk] = __ushort_as_bfloat16(l);
    }
}

// ============================================================
// bf16x3 mma.sync GEMM: CTA 128x128, 512 threads (16 warps, 32x32 each),
// K=1024 in 32 chunks of 32, double-buffered smem, padded 80B rows.
// ============================================================
#define TILE_BYTES 10240            // 128 rows * 80 B
#define BUF_BYTES  (4 * TILE_BYTES) // Ah, Al, Bh, Bl
#define GEMM_SMEM  (2 * BUF_BYTES)  // 81920
#define NCHUNK     32

__device__ __forceinline__ void gemm_mainloop(
    const __nv_bfloat16* __restrict__ Ah, const __nv_bfloat16* __restrict__ Al,
    const __nv_bfloat16* __restrict__ Bh, const __nv_bfloat16* __restrict__ Bl,
    float acc[2][4][4], char* smem)
{
    const uint32_t smem_base = smem_to_u32(smem);
    const int tid  = threadIdx.x;
    const int lane = tid & 31;
    const int wid  = tid >> 5;
    const int wr   = wid >> 2;        // 0..3
    const int wc   = wid & 3;         // 0..3
    const int m0   = blockIdx.y * 128;
    const int n0   = blockIdx.x * 128;

    // loader mapping: 128 threads per tile
    const int ltile = tid >> 7;       // 0:Ah 1:Al 2:Bh 3:Bl
    const int tt    = tid & 127;
    const int kg    = tt & 3;         // 16B group within 64B row-chunk
    const int row0  = tt >> 2;        // 0..31

    const __nv_bfloat16* gbase;
    if      (ltile == 0) gbase = Ah + (size_t)m0 * DIM;
    else if (ltile == 1) gbase = Al + (size_t)m0 * DIM;
    else if (ltile == 2) gbase = Bh + (size_t)n0 * DIM;
    else                 gbase = Bl + (size_t)n0 * DIM;

    char* s_tile = smem + ltile * TILE_BYTES;

    uint4 stage[4];
    #pragma unroll
    for (int i = 0; i < 4; i++) {
        const int row = row0 + i * 32;
        stage[i] = *(const uint4*)(gbase + (size_t)row * DIM + kg * 8);
    }
    #pragma unroll
    for (int i = 0; i < 4; i++) {
        const int row = row0 + i * 32;
        *(uint4*)(s_tile + row * 80 + kg * 16) = stage[i];
    }
    __syncthreads();

    const int arow = (lane & 7) + ((lane >> 3) & 1) * 8;
    const int acol = ((lane >> 4) & 1) * 16;
    const int brow = (lane & 7) + ((lane >> 4) & 1) * 8;
    const int bcol = ((lane >> 3) & 1) * 16;

    const uint32_t a_lane = (uint32_t)((wr * 32 + arow) * 80 + acol);
    const uint32_t b_lane = (uint32_t)(2 * TILE_BYTES + (wc * 32 + brow) * 80 + bcol);

    for (int c = 0; c < NCHUNK; c++) {
        const uint32_t buf = smem_base + (uint32_t)(c & 1) * BUF_BYTES;

        if (c + 1 < NCHUNK) {
            #pragma unroll
            for (int i = 0; i < 4; i++) {
                const int row = row0 + i * 32;
                stage[i] = *(const uint4*)(gbase + (size_t)row * DIM +
                                           (c + 1) * 32 + kg * 8);
            }
        }

        #pragma unroll
        for (int ks = 0; ks < 2; ks++) {
            uint32_t ah[2][4], al[2][4], bh[2][4], bl[2][4];
            #pragma unroll
            for (int mt = 0; mt < 2; mt++) {
                const uint32_t aaddr = buf + a_lane + mt * 16 * 80 + ks * 32;
                ldsm4(ah[mt], aaddr);
                ldsm4(al[mt], aaddr + TILE_BYTES);
            }
            #pragma unroll
            for (int nt = 0; nt < 2; nt++) {
                const uint32_t baddr = buf + b_lane + nt * 16 * 80 + ks * 32;
                ldsm4(bh[nt], baddr);
                ldsm4(bl[nt], baddr + TILE_BYTES);
            }
            #pragma unroll
            for (int mt = 0; mt < 2; mt++)
                #pragma unroll
                for (int nj = 0; nj < 4; nj++) {
                    const uint32_t b0h = bh[nj >> 1][(nj & 1) * 2];
                    const uint32_t b1h = bh[nj >> 1][(nj & 1) * 2 + 1];
                    const uint32_t b0l = bl[nj >> 1][(nj & 1) * 2];
                    const uint32_t b1l = bl[nj >> 1][(nj & 1) * 2 + 1];
                    mma_bf16(acc[mt][nj], ah[mt], b0h, b1h);
                    mma_bf16(acc[mt][nj], ah[mt], b0l, b1l);
                    mma_bf16(acc[mt][nj], al[mt], b0h, b1h);
                }
        }

        if (c + 1 < NCHUNK) {
            char* nbuf = smem + ((c + 1) & 1) * BUF_BYTES + ltile * TILE_BYTES;
            #pragma unroll
            for (int i = 0; i < 4; i++) {
                const int row = row0 + i * 32;
                *(uint4*)(nbuf + row * 80 + kg * 16) = stage[i];
            }
        }
        __syncthreads();
    }
}

// ============================================================
// Kernel 1: qkv = x @ w_qkv -> scatter to g_q/g_k/g_v [B,H,S,D]
// grid (24, 64), 512 threads
// ============================================================
__global__ void __launch_bounds__(512, 1)
qkv_gemm_kernel()
{
    extern __shared__ __align__(16) char smem[];
    float acc[2][4][4] = {};
    gemm_mainloop(g_xh, g_xl, g_wqh, g_wql, acc, smem);

    const int lane = threadIdx.x & 31;
    const int wid  = threadIdx.x >> 5;
    const int wr   = wid >> 2, wc = wid & 3;
    const int m_base = blockIdx.y * 128 + wr * 32;
    const int n_base = blockIdx.x * 128 + wc * 32;

    #pragma unroll
    for (int mt = 0; mt < 2; mt++) {
        #pragma unroll
        for (int nj = 0; nj < 4; nj++) {
            const int n = n_base + nj * 8 + (lane & 3) * 2;
            const int three = n >> 10;
            const int h = (n >> 6) & 15;
            const int d = n & 63;
            float* dst = (three == 0) ? g_q : (three == 1) ? g_k : g_v;
            #pragma unroll
            for (int rs = 0; rs < 2; rs++) {
                const int m = m_base + mt * 16 + (lane >> 2) + rs * 8;
                const int b = m >> 11;
                const int s = m & 2047;
                float2 v = make_float2(acc[mt][nj][rs * 2], acc[mt][nj][rs * 2 + 1]);
                *(float2*)&dst[(((size_t)(b * NHEADS + h)) * SEQ + s) * HDIM + d] = v;
            }
        }
    }
}

// ============================================================
// Kernel 3: out = attn @ w_proj + bias
// grid (8, 64), 512 threads
// ============================================================
__global__ void __launch_bounds__(512, 1)
proj_gemm_kernel(const float* __restrict__ bias, float* __restrict__ out)
{
    extern __shared__ __align__(16) char smem[];
    float acc[2][4][4] = {};
    gemm_mainloop(g_ah, g_al, g_wph, g_wpl, acc, smem);

    const int lane = threadIdx.x & 31;
    const int wid  = threadIdx.x >> 5;
    const int wr   = wid >> 2, wc = wid & 3;
    const int m_base = blockIdx.y * 128 + wr * 32;
    const int n_base = blockIdx.x * 128 + wc * 32;

    #pragma unroll
    for (int mt = 0; mt < 2; mt++) {
        #pragma unroll
        for (int nj = 0; nj < 4; nj++) {
            const int n = n_base + nj * 8 + (lane & 3) * 2;
            const float2 bv = *(const float2*)&bias[n];
            #pragma unroll
            for (int rs = 0; rs < 2; rs++) {
                const int m = m_base + mt * 16 + (lane >> 2) + rs * 8;
                float2 v = make_float2(acc[mt][nj][rs * 2] + bv.x,
                                       acc[mt][nj][rs * 2 + 1] + bv.y);
                *(float2*)&out[(size_t)m * DIM + n] = v;
            }
        }
    }
}

// ============================================================
// Kernel 2: causal flash attention, 64x64 tiles, fp32;
// epilogue writes bf16 hi/lo for the proj GEMM.
// grid: (S/64, H, B), 256 threads
// ============================================================
__global__ void attn_kernel()
{
    extern __shared__ float sm[];
    float* Qs  = sm;
    float* Ks  = Qs + 4096;
    float* Vs  = Ks + 4096;
    float* Ss  = Vs + 4096;
    float* red  = Ss + 4096;
    float* red2 = red + 1024;
    float* m_s  = red2 + 1024;
    float* l_s  = m_s + 64;

    const int tid = threadIdx.x;
    const int ty  = tid >> 4;
    const int tx  = tid & 15;
    const int qt  = blockIdx.x;
    const int h   = blockIdx.y;
    const int b   = blockIdx.z;
    const size_t base = ((size_t)(b * NHEADS + h)) * SEQ * HDIM;
    const int q0 = qt * 64;

    for (int idx = tid; idx < 64 * 16; idx += 256) {
        const int row = idx >> 4;
        const int d4  = (idx & 15) << 2;
        float4 v = *(const float4*)&g_q[base + (size_t)(q0 + row) * HDIM + d4];
        Qs[(d4 + 0) * 64 + row] = v.x;
        Qs[(d4 + 1) * 64 + row] = v.y;
        Qs[(d4 + 2) * 64 + row] = v.z;
        Qs[(d4 + 3) * 64 + row] = v.w;
    }
    if (tid < 64) { m_s[tid] = -1e30f; l_s[tid] = 0.f; }

    float o[4][4] = {};

    for (int kt = 0; kt <= qt; kt++) {
        const int k0 = kt * 64;
        __syncthreads();
        for (int idx = tid; idx < 64 * 16; idx += 256) {
            const int row = idx >> 4;
            const int d4  = (idx & 15) << 2;
            float4 kv = *(const float4*)&g_k[base + (size_t)(k0 + row) * HDIM + d4];
            Ks[(d4 + 0) * 64 + row] = kv.x;
            Ks[(d4 + 1) * 64 + row] = kv.y;
            Ks[(d4 + 2) * 64 + row] = kv.z;
            Ks[(d4 + 3) * 64 + row] = kv.w;
            float4 vv = *(const float4*)&g_v[base + (size_t)(k0 + row) * HDIM + d4];
            *(float4*)&Vs[row * 64 + d4] = vv;
        }
        __syncthreads();

        float s[4][4] = {};
        #pragma unroll 4
        for (int d = 0; d < 64; d++) {
            float4 qv = *(const float4*)&Qs[d * 64 + 4 * ty];
            float4 kv = *(const float4*)&Ks[d * 64 + 4 * tx];
            const float qa[4] = {qv.x, qv.y, qv.z, qv.w};
            const float ka[4] = {kv.x, kv.y, kv.z, kv.w};
            #pragma unroll
            for (int r = 0; r < 4; r++)
                #pragma unroll
                for (int c = 0; c < 4; c++)
                    s[r][c] = fmaf(qa[r], ka[c], s[r][c]);
        }

        const bool diag = (kt == qt);
        float rmax[4];
        #pragma unroll
        for (int r = 0; r < 4; r++) {
            rmax[r] = -1e30f;
            const int row_g = q0 + 4 * ty + r;
            #pragma unroll
            for (int c = 0; c < 4; c++) {
                s[r][c] *= SCALE;
                if (diag && (k0 + 4 * tx + c) > row_g) s[r][c] = -1e30f;
                rmax[r] = fmaxf(rmax[r], s[r][c]);
            }
            red[(4 * ty + r) * 16 + tx] = rmax[r];
        }
        __syncthreads();

        float alpha[4], mnew[4];
        #pragma unroll
        for (int r = 0; r < 4; r++) {
            const int i = 4 * ty + r;
            float mt = red[i * 16];
            #pragma unroll
            for (int t = 1; t < 16; t++) mt = fmaxf(mt, red[i * 16 + t]);
            const float mo = m_s[i];
            mnew[r]  = fmaxf(mo, mt);
            alpha[r] = __expf(mo - mnew[r]);

            float4 p;
            p.x = __expf(s[r][0] - mnew[r]);
            p.y = __expf(s[r][1] - mnew[r]);
            p.z = __expf(s[r][2] - mnew[r]);
            p.w = __expf(s[r][3] - mnew[r]);
            *(float4*)&Ss[i * 64 + 4 * tx] = p;
            red2[i * 16 + tx] = p.x + p.y + p.z + p.w;

            #pragma unroll
            for (int c = 0; c < 4; c++) o[r][c] *= alpha[r];
        }
        __syncthreads();

        if (tx == 0) {
            #pragma unroll
            for (int r = 0; r < 4; r++) {
                const int i = 4 * ty + r;
                float sum = 0.f;
                #pragma unroll
                for (int t = 0; t < 16; t++) sum += red2[i * 16 + t];
                l_s[i] = l_s[i] * alpha[r] + sum;
                m_s[i] = mnew[r];
            }
        }

        #pragma unroll 4
        for (int kk = 0; kk < 64; kk++) {
            float4 vv = *(const float4*)&Vs[kk * 64 + 4 * tx];
            #pragma unroll
            for (int r = 0; r < 4; r++) {
                const float p = Ss[(4 * ty + r) * 64 + kk];
                o[r][0] = fmaf(p, vv.x, o[r][0]);
                o[r][1] = fmaf(p, vv.y, o[r][1]);
                o[r][2] = fmaf(p, vv.z, o[r][2]);
                o[r][3] = fmaf(p, vv.w, o[r][3]);
            }
        }
    }
    __syncthreads();

    #pragma unroll
    for (int r = 0; r < 4; r++) {
        const int i = 4 * ty + r;
        const float inv = 1.f / l_s[i];
        const size_t off = ((size_t)(b * SEQ + q0 + i)) * DIM + h * HDIM + 4 * tx;
        unsigned short hh[4], ll[4];
        bf16split(o[r][0] * inv, hh[0], ll[0]);
        bf16split(o[r][1] * inv, hh[1], ll[1]);
        bf16split(o[r][2] * inv, hh[2], ll[2]);
        bf16split(o[r][3] * inv, hh[3], ll[3]);
        *(uint2*)&g_ah[off] = make_uint2((uint32_t)hh[0] | ((uint32_t)hh[1] << 16),
                                         (uint32_t)hh[2] | ((uint32_t)hh[3] << 16));
        *(uint2*)&g_al[off] = make_uint2((uint32_t)ll[0] | ((uint32_t)ll[1] << 16),
                                         (uint32_t)ll[2] | ((uint32_t)ll[3] << 16));
    }
}

// ============================================================
extern "C" void kernel_launch(void* const* d_in, const int* in_sizes, int n_in,
                              void* d_out, int out_size)
{
    const float* x      = (const float*)d_in[0];
    const float* w_qkv  = (const float*)d_in[1];
    const float* w_proj = (const float*)d_in[2];
    const float* b_proj = (const float*)d_in[3];
    float* out = (float*)d_out;

    // -- preprocess: split x; transpose+split weights --
    {
        __nv_bfloat16 *xh, *xl, *wqh, *wql, *wph, *wpl;
        cudaGetSymbolAddress((void**)&xh,  g_xh);
        cudaGetSymbolAddress((void**)&xl,  g_xl);
        cudaGetSymbolAddress((void**)&wqh, g_wqh);
        cudaGetSymbolAddress((void**)&wql, g_wql);
        cudaGetSymbolAddress((void**)&wph, g_wph);
        cudaGetSymbolAddress((void**)&wpl, g_wpl);

        const int n4 = NTOK * DIM / 4;   // 2M
        convert_split_kernel<<<(n4 + 511) / 512, 512>>>(x, xh, xl, n4);

        dim3 blk(32, 8);
        transpose_split_kernel<<<dim3(3 * DIM / 32, DIM / 32), blk>>>(
            w_qkv, wqh, wql, DIM, 3 * DIM);
        transpose_split_kernel<<<dim3(DIM / 32, DIM / 32), blk>>>(
            w_proj, wph, wpl, DIM, DIM);
    }

    // -- QKV GEMM (bf16x3 mma.sync): M=8192, N=3072, K=1024 --
    {
        cudaFuncSetAttribute(qkv_gemm_kernel,
                             cudaFuncAttributeMaxDynamicSharedMemorySize, GEMM_SMEM);
        dim3 grid(3 * DIM / 128, NTOK / 128);
        qkv_gemm_kernel<<<grid, 512, GEMM_SMEM>>>();
    }

    // -- attention (fp32) --
    {
        const int smem_bytes = (4 * 4096 + 2 * 1024 + 128) * (int)sizeof(float);
        cudaFuncSetAttribute(attn_kernel,
                             cudaFuncAttributeMaxDynamicSharedMemorySize, smem_bytes);
        dim3 grid(SEQ / 64, NHEADS, BATCH);
        attn_kernel<<<grid, 256, smem_bytes>>>();
    }

    // -- projection GEMM (bf16x3 mma.sync): M=8192, N=1024, K=1024 --
    {
        cudaFuncSetAttribute(proj_gemm_kernel,
                             cudaFuncAttributeMaxDynamicSharedMemorySize, GEMM_SMEM);
        dim3 grid(DIM / 128, NTOK / 128);
        proj_gemm_kernel<<<grid, 512, GEMM_SMEM>>>(b_proj, out);
    }
}

// round 6
// speedup vs baseline: 2.9642x; 1.9711x over previous
#include <cuda_runtime.h>
#include <cuda_bf16.h>
#include <cstdint>

#define DIM     1024
#define NHEADS  16
#define HDIM    64
#define SEQ     2048
#define BATCH   4
#define NTOK    (BATCH * SEQ)          // 8192
// SCALE * log2(e) folded into Q so softmax uses exp2
#define QSCALE  0.18033688011112042f
#define NEGBIG  -1e9f

// -------- scratch (device globals: allocation-free) --------
__device__ __nv_bfloat16 g_qh[(size_t)BATCH * NHEADS * SEQ * HDIM]; // [B,H,S,D]
__device__ __nv_bfloat16 g_ql[(size_t)BATCH * NHEADS * SEQ * HDIM];
__device__ __nv_bfloat16 g_kh[(size_t)BATCH * NHEADS * SEQ * HDIM];
__device__ __nv_bfloat16 g_kl[(size_t)BATCH * NHEADS * SEQ * HDIM];
__device__ __nv_bfloat16 g_vh[(size_t)BATCH * NHEADS * HDIM * SEQ]; // [B,H,D,S] !
__device__ __nv_bfloat16 g_vl[(size_t)BATCH * NHEADS * HDIM * SEQ];
__device__ __nv_bfloat16 g_xh[(size_t)NTOK * DIM];             // x hi/lo
__device__ __nv_bfloat16 g_xl[(size_t)NTOK * DIM];
__device__ __nv_bfloat16 g_wqh[(size_t)3 * DIM * DIM];         // w_qkv^T [n][k]
__device__ __nv_bfloat16 g_wql[(size_t)3 * DIM * DIM];
__device__ __nv_bfloat16 g_wph[(size_t)DIM * DIM];             // w_proj^T [n][k]
__device__ __nv_bfloat16 g_wpl[(size_t)DIM * DIM];
__device__ __nv_bfloat16 g_ah[(size_t)NTOK * DIM];             // attn out hi/lo
__device__ __nv_bfloat16 g_al[(size_t)NTOK * DIM];

// ============================================================
// helpers
// ============================================================
__device__ __forceinline__ uint32_t smem_to_u32(const void* p) {
    uint32_t a;
    asm("{ .reg .u64 t; cvta.to.shared.u64 t, %1; cvt.u32.u64 %0, t; }"
        : "=r"(a) : "l"(p));
    return a;
}

__device__ __forceinline__ void bf16split(float v, unsigned short& h, unsigned short& l) {
    __nv_bfloat16 hb = __float2bfloat16(v);
    h = __bfloat16_as_ushort(hb);
    l = __bfloat16_as_ushort(__float2bfloat16(v - __bfloat162float(hb)));
}

// pack 2 floats into bf16x2 hi + residual bf16x2 lo ({lo16=x, hi16=y})
__device__ __forceinline__ void packsplit2(float x, float y, uint32_t& hi, uint32_t& lo) {
    uint32_t h;
    asm("cvt.rn.bf16x2.f32 %0, %1, %2;" : "=r"(h) : "f"(y), "f"(x));
    float fx = __uint_as_float(h << 16);
    float fy = __uint_as_float(h & 0xFFFF0000u);
    uint32_t l;
    float rx = x - fx, ry = y - fy;
    asm("cvt.rn.bf16x2.f32 %0, %1, %2;" : "=r"(l) : "f"(ry), "f"(rx));
    hi = h; lo = l;
}

__device__ __forceinline__ float ex2(float x) {
    float y;
    asm("ex2.approx.f32 %0, %1;" : "=f"(y) : "f"(x));
    return y;
}

__device__ __forceinline__ void ldsm4(uint32_t r[4], uint32_t addr) {
    asm volatile("ldmatrix.sync.aligned.m8n8.x4.shared.b16 {%0,%1,%2,%3}, [%4];"
        : "=r"(r[0]), "=r"(r[1]), "=r"(r[2]), "=r"(r[3]) : "r"(addr));
}

__device__ __forceinline__ void mma_bf16(float d[4], const uint32_t a[4],
                                         uint32_t b0, uint32_t b1) {
    asm volatile(
        "mma.sync.aligned.m16n8k16.row.col.f32.bf16.bf16.f32 "
        "{%0,%1,%2,%3}, {%4,%5,%6,%7}, {%8,%9}, {%0,%1,%2,%3};"
        : "+f"(d[0]), "+f"(d[1]), "+f"(d[2]), "+f"(d[3])
        : "r"(a[0]), "r"(a[1]), "r"(a[2]), "r"(a[3]), "r"(b0), "r"(b1));
}

// ============================================================
// Preprocess kernels
// ============================================================
__global__ void convert_split_kernel(const float* __restrict__ in,
                                     __nv_bfloat16* __restrict__ hi,
                                     __nv_bfloat16* __restrict__ lo, int n4)
{
    const int i = blockIdx.x * blockDim.x + threadIdx.x;
    if (i >= n4) return;
    float4 v = ((const float4*)in)[i];
    unsigned short h[4], l[4];
    bf16split(v.x, h[0], l[0]); bf16split(v.y, h[1], l[1]);
    bf16split(v.z, h[2], l[2]); bf16split(v.w, h[3], l[3]);
    ((uint2*)hi)[i] = make_uint2((uint32_t)h[0] | ((uint32_t)h[1] << 16),
                                 (uint32_t)h[2] | ((uint32_t)h[3] << 16));
    ((uint2*)lo)[i] = make_uint2((uint32_t)l[0] | ((uint32_t)l[1] << 16),
                                 (uint32_t)l[2] | ((uint32_t)l[3] << 16));
}

// in [K][N] fp32 -> out hi/lo [N][K] bf16
__global__ void transpose_split_kernel(const float* __restrict__ in,
                                       __nv_bfloat16* __restrict__ hiT,
                                       __nv_bfloat16* __restrict__ loT,
                                       int K, int N)
{
    __shared__ float t[32][33];
    const int tx = threadIdx.x, ty = threadIdx.y;
    const int k0 = blockIdx.y * 32, n0 = blockIdx.x * 32;
    #pragma unroll
    for (int j = 0; j < 4; j++)
        t[ty + j * 8][tx] = in[(size_t)(k0 + ty + j * 8) * N + n0 + tx];
    __syncthreads();
    #pragma unroll
    for (int j = 0; j < 4; j++) {
        const int nn = n0 + ty + j * 8;
        const int kk = k0 + tx;
        unsigned short h, l;
        bf16split(t[tx][ty + j * 8], h, l);
        hiT[(size_t)nn * K + kk] = __ushort_as_bfloat16(h);
        loT[(size_t)nn * K + kk] = __ushort_as_bfloat16(l);
    }
}

// ============================================================
// bf16x3 mma.sync GEMM: CTA 128x128, 512 threads (16 warps, 32x32 each),
// K=1024 in 32 chunks of 32, double-buffered smem, padded 80B rows.
// ============================================================
#define TILE_BYTES 10240            // 128 rows * 80 B
#define BUF_BYTES  (4 * TILE_BYTES) // Ah, Al, Bh, Bl
#define GEMM_SMEM  (2 * BUF_BYTES)  // 81920
#define NCHUNK     32

__device__ __forceinline__ void gemm_mainloop(
    const __nv_bfloat16* __restrict__ Ah, const __nv_bfloat16* __restrict__ Al,
    const __nv_bfloat16* __restrict__ Bh, const __nv_bfloat16* __restrict__ Bl,
    float acc[2][4][4], char* smem)
{
    const uint32_t smem_base = smem_to_u32(smem);
    const int tid  = threadIdx.x;
    const int lane = tid & 31;
    const int wid  = tid >> 5;
    const int wr   = wid >> 2;
    const int wc   = wid & 3;
    const int m0   = blockIdx.y * 128;
    const int n0   = blockIdx.x * 128;

    const int ltile = tid >> 7;
    const int tt    = tid & 127;
    const int kg    = tt & 3;
    const int row0  = tt >> 2;

    const __nv_bfloat16* gbase;
    if      (ltile == 0) gbase = Ah + (size_t)m0 * DIM;
    else if (ltile == 1) gbase = Al + (size_t)m0 * DIM;
    else if (ltile == 2) gbase = Bh + (size_t)n0 * DIM;
    else                 gbase = Bl + (size_t)n0 * DIM;

    char* s_tile = smem + ltile * TILE_BYTES;

    uint4 stage[4];
    #pragma unroll
    for (int i = 0; i < 4; i++) {
        const int row = row0 + i * 32;
        stage[i] = *(const uint4*)(gbase + (size_t)row * DIM + kg * 8);
    }
    #pragma unroll
    for (int i = 0; i < 4; i++) {
        const int row = row0 + i * 32;
        *(uint4*)(s_tile + row * 80 + kg * 16) = stage[i];
    }
    __syncthreads();

    const int arow = (lane & 7) + ((lane >> 3) & 1) * 8;
    const int acol = ((lane >> 4) & 1) * 16;
    const int brow = (lane & 7) + ((lane >> 4) & 1) * 8;
    const int bcol = ((lane >> 3) & 1) * 16;

    const uint32_t a_lane = (uint32_t)((wr * 32 + arow) * 80 + acol);
    const uint32_t b_lane = (uint32_t)(2 * TILE_BYTES + (wc * 32 + brow) * 80 + bcol);

    for (int c = 0; c < NCHUNK; c++) {
        const uint32_t buf = smem_base + (uint32_t)(c & 1) * BUF_BYTES;

        if (c + 1 < NCHUNK) {
            #pragma unroll
            for (int i = 0; i < 4; i++) {
                const int row = row0 + i * 32;
                stage[i] = *(const uint4*)(gbase + (size_t)row * DIM +
                                           (c + 1) * 32 + kg * 8);
            }
        }

        #pragma unroll
        for (int ks = 0; ks < 2; ks++) {
            uint32_t ah[2][4], al[2][4], bh[2][4], bl[2][4];
            #pragma unroll
            for (int mt = 0; mt < 2; mt++) {
                const uint32_t aaddr = buf + a_lane + mt * 16 * 80 + ks * 32;
                ldsm4(ah[mt], aaddr);
                ldsm4(al[mt], aaddr + TILE_BYTES);
            }
            #pragma unroll
            for (int nt = 0; nt < 2; nt++) {
                const uint32_t baddr = buf + b_lane + nt * 16 * 80 + ks * 32;
                ldsm4(bh[nt], baddr);
                ldsm4(bl[nt], baddr + TILE_BYTES);
            }
            #pragma unroll
            for (int mt = 0; mt < 2; mt++)
                #pragma unroll
                for (int nj = 0; nj < 4; nj++) {
                    const uint32_t b0h = bh[nj >> 1][(nj & 1) * 2];
                    const uint32_t b1h = bh[nj >> 1][(nj & 1) * 2 + 1];
                    const uint32_t b0l = bl[nj >> 1][(nj & 1) * 2];
                    const uint32_t b1l = bl[nj >> 1][(nj & 1) * 2 + 1];
                    mma_bf16(acc[mt][nj], ah[mt], b0h, b1h);
                    mma_bf16(acc[mt][nj], ah[mt], b0l, b1l);
                    mma_bf16(acc[mt][nj], al[mt], b0h, b1h);
                }
        }

        if (c + 1 < NCHUNK) {
            char* nbuf = smem + ((c + 1) & 1) * BUF_BYTES + ltile * TILE_BYTES;
            #pragma unroll
            for (int i = 0; i < 4; i++) {
                const int row = row0 + i * 32;
                *(uint4*)(nbuf + row * 80 + kg * 16) = stage[i];
            }
        }
        __syncthreads();
    }
}

// ============================================================
// Kernel 1: qkv GEMM -> Q/K bf16 hi/lo [B,H,S,D] (Q pre-scaled),
//           V bf16 hi/lo TRANSPOSED [B,H,D,S].
// ============================================================
__global__ void __launch_bounds__(512, 1)
qkv_gemm_kernel()
{
    extern __shared__ __align__(16) char smem[];
    float acc[2][4][4] = {};
    gemm_mainloop(g_xh, g_xl, g_wqh, g_wql, acc, smem);

    const int lane = threadIdx.x & 31;
    const int wid  = threadIdx.x >> 5;
    const int wr   = wid >> 2, wc = wid & 3;
    const int m_base = blockIdx.y * 128 + wr * 32;
    const int n_base = blockIdx.x * 128 + wc * 32;

    #pragma unroll
    for (int mt = 0; mt < 2; mt++) {
        #pragma unroll
        for (int nj = 0; nj < 4; nj++) {
            const int n = n_base + nj * 8 + (lane & 3) * 2;
            const int three = n >> 10;
            const int h = (n >> 6) & 15;
            const int d = n & 63;
            #pragma unroll
            for (int rs = 0; rs < 2; rs++) {
                const int m = m_base + mt * 16 + (lane >> 2) + rs * 8;
                const int b = m >> 11;
                const int s = m & 2047;
                const float x0 = acc[mt][nj][rs * 2];
                const float x1 = acc[mt][nj][rs * 2 + 1];
                if (three == 2) {
                    // V: scatter to [B,H,D,S]
                    unsigned short h0, l0, h1, l1;
                    bf16split(x0, h0, l0);
                    bf16split(x1, h1, l1);
                    const size_t tb = ((size_t)(b * NHEADS + h)) * HDIM * SEQ;
                    g_vh[tb + (size_t)d * SEQ + s]       = __ushort_as_bfloat16(h0);
                    g_vl[tb + (size_t)d * SEQ + s]       = __ushort_as_bfloat16(l0);
                    g_vh[tb + (size_t)(d + 1) * SEQ + s] = __ushort_as_bfloat16(h1);
                    g_vl[tb + (size_t)(d + 1) * SEQ + s] = __ushort_as_bfloat16(l1);
                } else {
                    __nv_bfloat16* dsth = (three == 0) ? g_qh : g_kh;
                    __nv_bfloat16* dstl = (three == 0) ? g_ql : g_kl;
                    const float sc = (three == 0) ? QSCALE : 1.0f;
                    uint32_t hi, lo;
                    packsplit2(x0 * sc, x1 * sc, hi, lo);
                    const size_t idx = (((size_t)(b * NHEADS + h)) * SEQ + s) * HDIM + d;
                    *(uint32_t*)&dsth[idx] = hi;
                    *(uint32_t*)&dstl[idx] = lo;
                }
            }
        }
    }
}

// ============================================================
// Kernel 3: out = attn @ w_proj + bias
// ============================================================
__global__ void __launch_bounds__(512, 1)
proj_gemm_kernel(const float* __restrict__ bias, float* __restrict__ out)
{
    extern __shared__ __align__(16) char smem[];
    float acc[2][4][4] = {};
    gemm_mainloop(g_ah, g_al, g_wph, g_wpl, acc, smem);

    const int lane = threadIdx.x & 31;
    const int wid  = threadIdx.x >> 5;
    const int wr   = wid >> 2, wc = wid & 3;
    const int m_base = blockIdx.y * 128 + wr * 32;
    const int n_base = blockIdx.x * 128 + wc * 32;

    #pragma unroll
    for (int mt = 0; mt < 2; mt++) {
        #pragma unroll
        for (int nj = 0; nj < 4; nj++) {
            const int n = n_base + nj * 8 + (lane & 3) * 2;
            const float2 bv = *(const float2*)&bias[n];
            #pragma unroll
            for (int rs = 0; rs < 2; rs++) {
                const int m = m_base + mt * 16 + (lane >> 2) + rs * 8;
                float2 v = make_float2(acc[mt][nj][rs * 2] + bv.x,
                                       acc[mt][nj][rs * 2 + 1] + bv.y);
                *(float2*)&out[(size_t)m * DIM + n] = v;
            }
        }
    }
}

// ============================================================
// Kernel 2: tensor-core causal flash attention.
// CTA = 128 q-rows, kv tile 64, 8 warps (16 q-rows each), bf16x3 MMAs.
// V smem tile is [d][kv] (from V^T global) -> non-trans ldsm4 B-operand.
// grid (16, 16, 4), 256 threads, 2 CTAs/SM.
// ============================================================
#define SROW    144                 // smem row stride (64 bf16 = 128B + 16 pad)
#define QH_OFF  0
#define QL_OFF  (128 * SROW)        // 18432
#define KH_OFF  (2 * 128 * SROW)    // 36864
#define KL_OFF  (KH_OFF + 64 * SROW)
#define VH_OFF  (KL_OFF + 64 * SROW)
#define VL_OFF  (VH_OFF + 64 * SROW)
#define ATT_SMEM (VL_OFF + 64 * SROW)   // 73728

__global__ void __launch_bounds__(256, 2) attn_kernel()
{
    extern __shared__ __align__(16) char sm[];
    const uint32_t sbase = smem_to_u32(sm);

    const int tid  = threadIdx.x;
    const int lane = tid & 31;
    const int w    = tid >> 5;
    const int qt   = gridDim.x - 1 - blockIdx.x;   // big tiles first
    const int h    = blockIdx.y;
    const int b    = blockIdx.z;
    const int q0   = qt * 128;
    const size_t bh = ((size_t)(b * NHEADS + h)) * SEQ * HDIM;

    // ---- load Q hi/lo tile ----
    #pragma unroll
    for (int j = 0; j < 8; j++) {
        const int i = tid + j * 256;          // 0..2047
        const int arr = i >> 10;              // 0 hi, 1 lo
        const int t   = i & 1023;
        const int row = t >> 3, ch = t & 7;
        const __nv_bfloat16* g = arr ? g_ql : g_qh;
        uint4 v = *(const uint4*)&g[bh + (size_t)(q0 + row) * HDIM + ch * 8];
        *(uint4*)(sm + (arr ? QL_OFF : QH_OFF) + row * SROW + ch * 16) = v;
    }

    // lane fragments addressing
    const int a_row  = (lane & 7) + ((lane >> 3) & 1) * 8;
    const int a_kbit = (lane >> 4) & 1;
    const uint32_t q_lane = sbase + QH_OFF + (w * 16 + a_row) * SROW + a_kbit * 16;
    const int b_row  = (lane & 7) + ((lane >> 4) & 1) * 8;   // B-operand row (n)
    const int b_kbit = (lane >> 3) & 1;                       // +8 k

    const int row_lo    = q0 + w * 16 + (lane >> 2);
    const int warp_rmin = q0 + w * 16;
    const int warp_rmax = warp_rmin + 15;
    const int nkv = 2 * qt + 2;

    float o[8][4];
    #pragma unroll
    for (int i = 0; i < 8; i++)
        #pragma unroll
        for (int j = 0; j < 4; j++) o[i][j] = 0.f;
    float m_lo = NEGBIG, m_hi = NEGBIG, l_lo = 0.f, l_hi = 0.f;

    for (int kt = 0; kt < nkv; kt++) {
        const int kv0 = kt * 64;
        __syncthreads();
        // ---- load K hi/lo [kv][d] and V^T hi/lo [d][kv] tiles ----
        #pragma unroll
        for (int j = 0; j < 8; j++) {
            const int i = tid + j * 256;
            const int arr = i >> 9;           // 0 kh, 1 kl, 2 vh, 3 vl
            const int t   = i & 511;
            const int row = t >> 3, ch = t & 7;
            uint4 v;
            int off;
            if (arr < 2) {
                const __nv_bfloat16* g = (arr == 0) ? g_kh : g_kl;
                v = *(const uint4*)&g[bh + (size_t)(kv0 + row) * HDIM + ch * 8];
                off = (arr == 0) ? KH_OFF : KL_OFF;
            } else {
                const __nv_bfloat16* g = (arr == 2) ? g_vh : g_vl;
                v = *(const uint4*)&g[bh + (size_t)row * SEQ + kv0 + ch * 8];
                off = (arr == 2) ? VH_OFF : VL_OFF;
            }
            *(uint4*)(sm + off + row * SROW + ch * 16) = v;
        }
        __syncthreads();

        if (kv0 <= warp_rmax) {
            // ---- S = Q K^T (bf16x3) ----
            float sc[8][4];
            #pragma unroll
            for (int i = 0; i < 8; i++)
                #pragma unroll
                for (int j = 0; j < 4; j++) sc[i][j] = 0.f;

            #pragma unroll
            for (int ks = 0; ks < 4; ks++) {
                uint32_t qh[4], ql[4];
                ldsm4(qh, q_lane + ks * 32);
                ldsm4(ql, q_lane + ks * 32 + (QL_OFF - QH_OFF));
                #pragma unroll
                for (int kb = 0; kb < 4; kb++) {
                    uint32_t kh[4], kl[4];
                    const uint32_t kaddr = sbase + KH_OFF + (kb * 16 + b_row) * SROW +
                                           ks * 32 + b_kbit * 16;
                    ldsm4(kh, kaddr);
                    ldsm4(kl, kaddr + (KL_OFF - KH_OFF));
                    mma_bf16(sc[2 * kb],     qh, kh[0], kh[1]);
                    mma_bf16(sc[2 * kb],     qh, kl[0], kl[1]);
                    mma_bf16(sc[2 * kb],     ql, kh[0], kh[1]);
                    mma_bf16(sc[2 * kb + 1], qh, kh[2], kh[3]);
                    mma_bf16(sc[2 * kb + 1], qh, kl[2], kl[3]);
                    mma_bf16(sc[2 * kb + 1], ql, kh[2], kh[3]);
                }
            }

            // ---- causal mask ----
            if (kv0 + 63 > warp_rmin) {
                #pragma unroll
                for (int nj = 0; nj < 8; nj++) {
                    const int col = kv0 + nj * 8 + 2 * (lane & 3);
                    if (col     > row_lo)     sc[nj][0] = NEGBIG;
                    if (col + 1 > row_lo)     sc[nj][1] = NEGBIG;
                    if (col     > row_lo + 8) sc[nj][2] = NEGBIG;
                    if (col + 1 > row_lo + 8) sc[nj][3] = NEGBIG;
                }
            }

            // ---- row max (quad reduce) ----
            float mx0 = NEGBIG, mx1 = NEGBIG;
            #pragma unroll
            for (int nj = 0; nj < 8; nj++) {
                mx0 = fmaxf(mx0, fmaxf(sc[nj][0], sc[nj][1]));
                mx1 = fmaxf(mx1, fmaxf(sc[nj][2], sc[nj][3]));
            }
            mx0 = fmaxf(mx0, __shfl_xor_sync(0xffffffffu, mx0, 1));
            mx0 = fmaxf(mx0, __shfl_xor_sync(0xffffffffu, mx0, 2));
            mx1 = fmaxf(mx1, __shfl_xor_sync(0xffffffffu, mx1, 1));
            mx1 = fmaxf(mx1, __shfl_xor_sync(0xffffffffu, mx1, 2));

            const float mn0 = fmaxf(m_lo, mx0);
            const float mn1 = fmaxf(m_hi, mx1);
            const float al0 = ex2(m_lo - mn0);
            const float al1 = ex2(m_hi - mn1);
            m_lo = mn0; m_hi = mn1;

            #pragma unroll
            for (int dt = 0; dt < 8; dt++) {
                o[dt][0] *= al0; o[dt][1] *= al0;
                o[dt][2] *= al1; o[dt][3] *= al1;
            }
            l_lo *= al0; l_hi *= al1;

            // ---- p = exp2(s-m), pack hi/lo, PV MMAs (V smem is [d][kv]) ----
            #pragma unroll
            for (int ks = 0; ks < 4; ks++) {
                uint32_t pah[4], pal[4];
                float s0 = 0.f, s1 = 0.f;
                #pragma unroll
                for (int half = 0; half < 2; half++) {
                    const int nj = 2 * ks + half;
                    float p0 = ex2(sc[nj][0] - mn0);
                    float p1 = ex2(sc[nj][1] - mn0);
                    float p2 = ex2(sc[nj][2] - mn1);
                    float p3 = ex2(sc[nj][3] - mn1);
                    s0 += p0 + p1; s1 += p2 + p3;
                    packsplit2(p0, p1, pah[half * 2],     pal[half * 2]);
                    packsplit2(p2, p3, pah[half * 2 + 1], pal[half * 2 + 1]);
                }
                l_lo += s0; l_hi += s1;

                #pragma unroll
                for (int db = 0; db < 4; db++) {
                    uint32_t vh[4], vl[4];
                    // rows = d (n operand), cols = kv (k); chunk k = ks*16
                    const uint32_t vaddr = sbase + VH_OFF + (db * 16 + b_row) * SROW +
                                           ks * 32 + b_kbit * 16;
                    ldsm4(vh, vaddr);
                    ldsm4(vl, vaddr + (VL_OFF - VH_OFF));
                    mma_bf16(o[2 * db],     pah, vh[0], vh[1]);
                    mma_bf16(o[2 * db],     pal, vh[0], vh[1]);
                    mma_bf16(o[2 * db],     pah, vl[0], vl[1]);
                    mma_bf16(o[2 * db + 1], pah, vh[2], vh[3]);
                    mma_bf16(o[2 * db + 1], pal, vh[2], vh[3]);
                    mma_bf16(o[2 * db + 1], pah, vl[2], vl[3]);
                }
            }
        }
    }

    // ---- FIX: l is a per-thread partial over this thread's columns; the
    // softmax denominator needs the full row sum -> quad-reduce (lanes
    // sharing the same row are lane^1, lane^2). m/alpha are already
    // quad-uniform so deferring this reduction to here is exact. ----
    l_lo += __shfl_xor_sync(0xffffffffu, l_lo, 1);
    l_lo += __shfl_xor_sync(0xffffffffu, l_lo, 2);
    l_hi += __shfl_xor_sync(0xffffffffu, l_hi, 1);
    l_hi += __shfl_xor_sync(0xffffffffu, l_hi, 2);

    // ---- epilogue: normalize, bf16 hi/lo split into g_ah/g_al ----
    const float inv0 = 1.f / l_lo;
    const float inv1 = 1.f / l_hi;
    #pragma unroll
    for (int dt = 0; dt < 8; dt++) {
        const int c = h * HDIM + dt * 8 + 2 * (lane & 3);
        uint32_t hi, lo;
        packsplit2(o[dt][0] * inv0, o[dt][1] * inv0, hi, lo);
        size_t off = ((size_t)(b * SEQ + row_lo)) * DIM + c;
        *(uint32_t*)&g_ah[off] = hi;
        *(uint32_t*)&g_al[off] = lo;
        packsplit2(o[dt][2] * inv1, o[dt][3] * inv1, hi, lo);
        off = ((size_t)(b * SEQ + row_lo + 8)) * DIM + c;
        *(uint32_t*)&g_ah[off] = hi;
        *(uint32_t*)&g_al[off] = lo;
    }
}

// ============================================================
extern "C" void kernel_launch(void* const* d_in, const int* in_sizes, int n_in,
                              void* d_out, int out_size)
{
    const float* x      = (const float*)d_in[0];
    const float* w_qkv  = (const float*)d_in[1];
    const float* w_proj = (const float*)d_in[2];
    const float* b_proj = (const float*)d_in[3];
    float* out = (float*)d_out;

    // -- preprocess: split x; transpose+split weights --
    {
        __nv_bfloat16 *xh, *xl, *wqh, *wql, *wph, *wpl;
        cudaGetSymbolAddress((void**)&xh,  g_xh);
        cudaGetSymbolAddress((void**)&xl,  g_xl);
        cudaGetSymbolAddress((void**)&wqh, g_wqh);
        cudaGetSymbolAddress((void**)&wql, g_wql);
        cudaGetSymbolAddress((void**)&wph, g_wph);
        cudaGetSymbolAddress((void**)&wpl, g_wpl);

        const int n4 = NTOK * DIM / 4;
        convert_split_kernel<<<(n4 + 511) / 512, 512>>>(x, xh, xl, n4);

        dim3 blk(32, 8);
        transpose_split_kernel<<<dim3(3 * DIM / 32, DIM / 32), blk>>>(
            w_qkv, wqh, wql, DIM, 3 * DIM);
        transpose_split_kernel<<<dim3(DIM / 32, DIM / 32), blk>>>(
            w_proj, wph, wpl, DIM, DIM);
    }

    // -- QKV GEMM (bf16x3 mma.sync) --
    {
        cudaFuncSetAttribute(qkv_gemm_kernel,
                             cudaFuncAttributeMaxDynamicSharedMemorySize, GEMM_SMEM);
        dim3 grid(3 * DIM / 128, NTOK / 128);
        qkv_gemm_kernel<<<grid, 512, GEMM_SMEM>>>();
    }

    // -- attention (tensor-core bf16x3) --
    {
        cudaFuncSetAttribute(attn_kernel,
                             cudaFuncAttributeMaxDynamicSharedMemorySize, ATT_SMEM);
        dim3 grid(SEQ / 128, NHEADS, BATCH);
        attn_kernel<<<grid, 256, ATT_SMEM>>>();
    }

    // -- projection GEMM (bf16x3 mma.sync) --
    {
        cudaFuncSetAttribute(proj_gemm_kernel,
                             cudaFuncAttributeMaxDynamicSharedMemorySize, GEMM_SMEM);
        dim3 grid(DIM / 128, NTOK / 128);
        proj_gemm_kernel<<<grid, 512, GEMM_SMEM>>>(b_proj, out);
    }
}

// round 7
// speedup vs baseline: 3.2887x; 1.1095x over previous
#include <cuda_runtime.h>
#include <cuda_bf16.h>
#include <cstdint>

#define DIM     1024
#define NHEADS  16
#define HDIM    64
#define SEQ     2048
#define BATCH   4
#define NTOK    (BATCH * SEQ)          // 8192
// SCALE * log2(e) folded into Q so softmax uses exp2
#define QSCALE  0.18033688011112042f
#define NEGBIG  -1e9f

// -------- scratch (device globals: allocation-free) --------
__device__ __nv_bfloat16 g_qh[(size_t)BATCH * NHEADS * SEQ * HDIM]; // [B,H,S,D]
__device__ __nv_bfloat16 g_ql[(size_t)BATCH * NHEADS * SEQ * HDIM];
__device__ __nv_bfloat16 g_kh[(size_t)BATCH * NHEADS * SEQ * HDIM];
__device__ __nv_bfloat16 g_kl[(size_t)BATCH * NHEADS * SEQ * HDIM];
__device__ __nv_bfloat16 g_vh[(size_t)BATCH * NHEADS * HDIM * SEQ]; // [B,H,D,S] !
__device__ __nv_bfloat16 g_vl[(size_t)BATCH * NHEADS * HDIM * SEQ];
__device__ __nv_bfloat16 g_xh[(size_t)NTOK * DIM];             // x hi/lo
__device__ __nv_bfloat16 g_xl[(size_t)NTOK * DIM];
__device__ __nv_bfloat16 g_wqh[(size_t)3 * DIM * DIM];         // w_qkv^T [n][k]
__device__ __nv_bfloat16 g_wql[(size_t)3 * DIM * DIM];
__device__ __nv_bfloat16 g_wph[(size_t)DIM * DIM];             // w_proj^T [n][k]
__device__ __nv_bfloat16 g_wpl[(size_t)DIM * DIM];
__device__ __nv_bfloat16 g_ah[(size_t)NTOK * DIM];             // attn out hi/lo
__device__ __nv_bfloat16 g_al[(size_t)NTOK * DIM];

// ============================================================
// helpers
// ============================================================
__device__ __forceinline__ uint32_t smem_to_u32(const void* p) {
    uint32_t a;
    asm("{ .reg .u64 t; cvta.to.shared.u64 t, %1; cvt.u32.u64 %0, t; }"
        : "=r"(a) : "l"(p));
    return a;
}

__device__ __forceinline__ void bf16split(float v, unsigned short& h, unsigned short& l) {
    __nv_bfloat16 hb = __float2bfloat16(v);
    h = __bfloat16_as_ushort(hb);
    l = __bfloat16_as_ushort(__float2bfloat16(v - __bfloat162float(hb)));
}

// pack 2 floats into bf16x2 hi + residual bf16x2 lo ({lo16=x, hi16=y})
__device__ __forceinline__ void packsplit2(float x, float y, uint32_t& hi, uint32_t& lo) {
    uint32_t h;
    asm("cvt.rn.bf16x2.f32 %0, %1, %2;" : "=r"(h) : "f"(y), "f"(x));
    float fx = __uint_as_float(h << 16);
    float fy = __uint_as_float(h & 0xFFFF0000u);
    uint32_t l;
    float rx = x - fx, ry = y - fy;
    asm("cvt.rn.bf16x2.f32 %0, %1, %2;" : "=r"(l) : "f"(ry), "f"(rx));
    hi = h; lo = l;
}

__device__ __forceinline__ float ex2(float x) {
    float y;
    asm("ex2.approx.f32 %0, %1;" : "=f"(y) : "f"(x));
    return y;
}

__device__ __forceinline__ void ldsm4(uint32_t r[4], uint32_t addr) {
    asm volatile("ldmatrix.sync.aligned.m8n8.x4.shared.b16 {%0,%1,%2,%3}, [%4];"
        : "=r"(r[0]), "=r"(r[1]), "=r"(r[2]), "=r"(r[3]) : "r"(addr));
}

__device__ __forceinline__ void mma_bf16(float d[4], const uint32_t a[4],
                                         uint32_t b0, uint32_t b1) {
    asm volatile(
        "mma.sync.aligned.m16n8k16.row.col.f32.bf16.bf16.f32 "
        "{%0,%1,%2,%3}, {%4,%5,%6,%7}, {%8,%9}, {%0,%1,%2,%3};"
        : "+f"(d[0]), "+f"(d[1]), "+f"(d[2]), "+f"(d[3])
        : "r"(a[0]), "r"(a[1]), "r"(a[2]), "r"(a[3]), "r"(b0), "r"(b1));
}

#define CP_ASYNC16(dst, src) \
    asm volatile("cp.async.cg.shared.global [%0], [%1], 16;" \
        :: "r"(dst), "l"(src) : "memory")
#define CP_COMMIT() asm volatile("cp.async.commit_group;" ::: "memory")
#define CP_WAIT(n)  asm volatile("cp.async.wait_group %0;" :: "n"(n) : "memory")

// ============================================================
// Preprocess kernels
// ============================================================
__global__ void convert_split_kernel(const float* __restrict__ in,
                                     __nv_bfloat16* __restrict__ hi,
                                     __nv_bfloat16* __restrict__ lo, int n4)
{
    const int i = blockIdx.x * blockDim.x + threadIdx.x;
    if (i >= n4) return;
    float4 v = ((const float4*)in)[i];
    unsigned short h[4], l[4];
    bf16split(v.x, h[0], l[0]); bf16split(v.y, h[1], l[1]);
    bf16split(v.z, h[2], l[2]); bf16split(v.w, h[3], l[3]);
    ((uint2*)hi)[i] = make_uint2((uint32_t)h[0] | ((uint32_t)h[1] << 16),
                                 (uint32_t)h[2] | ((uint32_t)h[3] << 16));
    ((uint2*)lo)[i] = make_uint2((uint32_t)l[0] | ((uint32_t)l[1] << 16),
                                 (uint32_t)l[2] | ((uint32_t)l[3] << 16));
}

// in [K][N] fp32 -> out hi/lo [N][K] bf16
__global__ void transpose_split_kernel(const float* __restrict__ in,
                                       __nv_bfloat16* __restrict__ hiT,
                                       __nv_bfloat16* __restrict__ loT,
                                       int K, int N)
{
    __shared__ float t[32][33];
    const int tx = threadIdx.x, ty = threadIdx.y;
    const int k0 = blockIdx.y * 32, n0 = blockIdx.x * 32;
    #pragma unroll
    for (int j = 0; j < 4; j++)
        t[ty + j * 8][tx] = in[(size_t)(k0 + ty + j * 8) * N + n0 + tx];
    __syncthreads();
    #pragma unroll
    for (int j = 0; j < 4; j++) {
        const int nn = n0 + ty + j * 8;
        const int kk = k0 + tx;
        unsigned short h, l;
        bf16split(t[tx][ty + j * 8], h, l);
        hiT[(size_t)nn * K + kk] = __ushort_as_bfloat16(h);
        loT[(size_t)nn * K + kk] = __ushort_as_bfloat16(l);
    }
}

// ============================================================
// bf16x3 mma.sync GEMM: CTA 128x128, 256 threads (8 warps, 64x32 each),
// K=1024 in 32 chunks of 32, cp.async double-buffered smem, 80B rows,
// 2 CTAs/SM.
// ============================================================
#define TILE_BYTES 10240            // 128 rows * 80 B
#define BUF_BYTES  (4 * TILE_BYTES) // Ah, Al, Bh, Bl
#define GEMM_SMEM  (2 * BUF_BYTES)  // 81920
#define NCHUNK     32

__device__ __forceinline__ void gemm_issue_chunk(
    const __nv_bfloat16* const gb[4], uint32_t dstbuf, int tid, int c)
{
    #pragma unroll
    for (int i = 0; i < 8; i++) {
        const int s    = tid + i * 256;
        const int tile = s >> 9;          // 512 segments per tile
        const int t2   = s & 511;
        const int row  = t2 >> 2;
        const int kg   = t2 & 3;
        const __nv_bfloat16* src = gb[tile] + (size_t)row * DIM + c * 32 + kg * 8;
        const uint32_t dst = dstbuf + tile * TILE_BYTES + row * 80 + kg * 16;
        CP_ASYNC16(dst, src);
    }
    CP_COMMIT();
}

__device__ __forceinline__ void gemm_mainloop(
    const __nv_bfloat16* __restrict__ Ah, const __nv_bfloat16* __restrict__ Al,
    const __nv_bfloat16* __restrict__ Bh, const __nv_bfloat16* __restrict__ Bl,
    float acc[4][4][4], char* smem)
{
    const uint32_t smem_base = smem_to_u32(smem);
    const int tid  = threadIdx.x;
    const int lane = tid & 31;
    const int wid  = tid >> 5;        // 0..7
    const int wr   = wid >> 2;        // 0..1 -> 64 rows each
    const int wc   = wid & 3;         // 0..3 -> 32 cols each
    const int m0   = blockIdx.y * 128;
    const int n0   = blockIdx.x * 128;

    const __nv_bfloat16* gb[4] = {
        Ah + (size_t)m0 * DIM, Al + (size_t)m0 * DIM,
        Bh + (size_t)n0 * DIM, Bl + (size_t)n0 * DIM };

    const int arow = (lane & 7) + ((lane >> 3) & 1) * 8;
    const int acol = ((lane >> 4) & 1) * 16;
    const int brow = (lane & 7) + ((lane >> 4) & 1) * 8;
    const int bcol = ((lane >> 3) & 1) * 16;

    const uint32_t a_lane = (uint32_t)((wr * 64 + arow) * 80 + acol);
    const uint32_t b_lane = (uint32_t)(2 * TILE_BYTES + (wc * 32 + brow) * 80 + bcol);

    gemm_issue_chunk(gb, smem_base, tid, 0);

    for (int c = 0; c < NCHUNK; c++) {
        const uint32_t buf = smem_base + (uint32_t)(c & 1) * BUF_BYTES;

        if (c + 1 < NCHUNK) {
            gemm_issue_chunk(gb, smem_base + (uint32_t)((c + 1) & 1) * BUF_BYTES,
                             tid, c + 1);
            CP_WAIT(1);
        } else {
            CP_WAIT(0);
        }
        __syncthreads();

        #pragma unroll
        for (int ks = 0; ks < 2; ks++) {
            uint32_t bh2[2][4], bl2[2][4];
            #pragma unroll
            for (int nt = 0; nt < 2; nt++) {
                const uint32_t baddr = buf + b_lane + nt * 16 * 80 + ks * 32;
                ldsm4(bh2[nt], baddr);
                ldsm4(bl2[nt], baddr + TILE_BYTES);
            }
            #pragma unroll
            for (int mt = 0; mt < 4; mt++) {
                uint32_t ah[4], al[4];
                const uint32_t aaddr = buf + a_lane + mt * 16 * 80 + ks * 32;
                ldsm4(ah, aaddr);
                ldsm4(al, aaddr + TILE_BYTES);
                #pragma unroll
                for (int nj = 0; nj < 4; nj++) {
                    const uint32_t b0h = bh2[nj >> 1][(nj & 1) * 2];
                    const uint32_t b1h = bh2[nj >> 1][(nj & 1) * 2 + 1];
                    const uint32_t b0l = bl2[nj >> 1][(nj & 1) * 2];
                    const uint32_t b1l = bl2[nj >> 1][(nj & 1) * 2 + 1];
                    mma_bf16(acc[mt][nj], ah, b0h, b1h);
                    mma_bf16(acc[mt][nj], ah, b0l, b1l);
                    mma_bf16(acc[mt][nj], al, b0h, b1h);
                }
            }
        }
        __syncthreads();   // all warps done reading buf before it is refilled
    }
}

// ============================================================
// Kernel 1: qkv GEMM -> Q/K bf16 hi/lo [B,H,S,D] (Q pre-scaled),
//           V bf16 hi/lo TRANSPOSED [B,H,D,S].
// grid (24, 64), 256 threads
// ============================================================
__global__ void __launch_bounds__(256, 2)
qkv_gemm_kernel()
{
    extern __shared__ __align__(16) char smem[];
    float acc[4][4][4] = {};
    gemm_mainloop(g_xh, g_xl, g_wqh, g_wql, acc, smem);

    const int lane = threadIdx.x & 31;
    const int wid  = threadIdx.x >> 5;
    const int wr   = wid >> 2, wc = wid & 3;
    const int m_base = blockIdx.y * 128 + wr * 64;
    const int n_base = blockIdx.x * 128 + wc * 32;

    #pragma unroll
    for (int mt = 0; mt < 4; mt++) {
        #pragma unroll
        for (int nj = 0; nj < 4; nj++) {
            const int n = n_base + nj * 8 + (lane & 3) * 2;
            const int three = n >> 10;
            const int h = (n >> 6) & 15;
            const int d = n & 63;
            #pragma unroll
            for (int rs = 0; rs < 2; rs++) {
                const int m = m_base + mt * 16 + (lane >> 2) + rs * 8;
                const int b = m >> 11;
                const int s = m & 2047;
                const float x0 = acc[mt][nj][rs * 2];
                const float x1 = acc[mt][nj][rs * 2 + 1];
                if (three == 2) {
                    // V: scatter to [B,H,D,S]
                    unsigned short h0, l0, h1, l1;
                    bf16split(x0, h0, l0);
                    bf16split(x1, h1, l1);
                    const size_t tb = ((size_t)(b * NHEADS + h)) * HDIM * SEQ;
                    g_vh[tb + (size_t)d * SEQ + s]       = __ushort_as_bfloat16(h0);
                    g_vl[tb + (size_t)d * SEQ + s]       = __ushort_as_bfloat16(l0);
                    g_vh[tb + (size_t)(d + 1) * SEQ + s] = __ushort_as_bfloat16(h1);
                    g_vl[tb + (size_t)(d + 1) * SEQ + s] = __ushort_as_bfloat16(l1);
                } else {
                    __nv_bfloat16* dsth = (three == 0) ? g_qh : g_kh;
                    __nv_bfloat16* dstl = (three == 0) ? g_ql : g_kl;
                    const float sc = (three == 0) ? QSCALE : 1.0f;
                    uint32_t hi, lo;
                    packsplit2(x0 * sc, x1 * sc, hi, lo);
                    const size_t idx = (((size_t)(b * NHEADS + h)) * SEQ + s) * HDIM + d;
                    *(uint32_t*)&dsth[idx] = hi;
                    *(uint32_t*)&dstl[idx] = lo;
                }
            }
        }
    }
}

// ============================================================
// Kernel 3: out = attn @ w_proj + bias
// grid (8, 64), 256 threads
// ============================================================
__global__ void __launch_bounds__(256, 2)
proj_gemm_kernel(const float* __restrict__ bias, float* __restrict__ out)
{
    extern __shared__ __align__(16) char smem[];
    float acc[4][4][4] = {};
    gemm_mainloop(g_ah, g_al, g_wph, g_wpl, acc, smem);

    const int lane = threadIdx.x & 31;
    const int wid  = threadIdx.x >> 5;
    const int wr   = wid >> 2, wc = wid & 3;
    const int m_base = blockIdx.y * 128 + wr * 64;
    const int n_base = blockIdx.x * 128 + wc * 32;

    #pragma unroll
    for (int mt = 0; mt < 4; mt++) {
        #pragma unroll
        for (int nj = 0; nj < 4; nj++) {
            const int n = n_base + nj * 8 + (lane & 3) * 2;
            const float2 bv = *(const float2*)&bias[n];
            #pragma unroll
            for (int rs = 0; rs < 2; rs++) {
                const int m = m_base + mt * 16 + (lane >> 2) + rs * 8;
                float2 v = make_float2(acc[mt][nj][rs * 2] + bv.x,
                                       acc[mt][nj][rs * 2 + 1] + bv.y);
                *(float2*)&out[(size_t)m * DIM + n] = v;
            }
        }
    }
}

// ============================================================
// Kernel 2: tensor-core causal flash attention (unchanged from R6 pass).
// CTA = 128 q-rows, kv tile 64, 8 warps (16 q-rows each), bf16x3 MMAs.
// V smem tile is [d][kv] (from V^T global) -> non-trans ldsm4 B-operand.
// grid (16, 16, 4), 256 threads, 2 CTAs/SM.
// ============================================================
#define SROW    144                 // smem row stride (64 bf16 = 128B + 16 pad)
#define QH_OFF  0
#define QL_OFF  (128 * SROW)        // 18432
#define KH_OFF  (2 * 128 * SROW)    // 36864
#define KL_OFF  (KH_OFF + 64 * SROW)
#define VH_OFF  (KL_OFF + 64 * SROW)
#define VL_OFF  (VH_OFF + 64 * SROW)
#define ATT_SMEM (VL_OFF + 64 * SROW)   // 73728

__global__ void __launch_bounds__(256, 2) attn_kernel()
{
    extern __shared__ __align__(16) char sm[];
    const uint32_t sbase = smem_to_u32(sm);

    const int tid  = threadIdx.x;
    const int lane = tid & 31;
    const int w    = tid >> 5;
    const int qt   = gridDim.x - 1 - blockIdx.x;   // big tiles first
    const int h    = blockIdx.y;
    const int b    = blockIdx.z;
    const int q0   = qt * 128;
    const size_t bh = ((size_t)(b * NHEADS + h)) * SEQ * HDIM;

    // ---- load Q hi/lo tile ----
    #pragma unroll
    for (int j = 0; j < 8; j++) {
        const int i = tid + j * 256;          // 0..2047
        const int arr = i >> 10;              // 0 hi, 1 lo
        const int t   = i & 1023;
        const int row = t >> 3, ch = t & 7;
        const __nv_bfloat16* g = arr ? g_ql : g_qh;
        uint4 v = *(const uint4*)&g[bh + (size_t)(q0 + row) * HDIM + ch * 8];
        *(uint4*)(sm + (arr ? QL_OFF : QH_OFF) + row * SROW + ch * 16) = v;
    }

    // lane fragments addressing
    const int a_row  = (lane & 7) + ((lane >> 3) & 1) * 8;
    const int a_kbit = (lane >> 4) & 1;
    const uint32_t q_lane = sbase + QH_OFF + (w * 16 + a_row) * SROW + a_kbit * 16;
    const int b_row  = (lane & 7) + ((lane >> 4) & 1) * 8;   // B-operand row (n)
    const int b_kbit = (lane >> 3) & 1;                       // +8 k

    const int row_lo    = q0 + w * 16 + (lane >> 2);
    const int warp_rmin = q0 + w * 16;
    const int warp_rmax = warp_rmin + 15;
    const int nkv = 2 * qt + 2;

    float o[8][4];
    #pragma unroll
    for (int i = 0; i < 8; i++)
        #pragma unroll
        for (int j = 0; j < 4; j++) o[i][j] = 0.f;
    float m_lo = NEGBIG, m_hi = NEGBIG, l_lo = 0.f, l_hi = 0.f;

    for (int kt = 0; kt < nkv; kt++) {
        const int kv0 = kt * 64;
        __syncthreads();
        // ---- load K hi/lo [kv][d] and V^T hi/lo [d][kv] tiles ----
        #pragma unroll
        for (int j = 0; j < 8; j++) {
            const int i = tid + j * 256;
            const int arr = i >> 9;           // 0 kh, 1 kl, 2 vh, 3 vl
            const int t   = i & 511;
            const int row = t >> 3, ch = t & 7;
            uint4 v;
            int off;
            if (arr < 2) {
                const __nv_bfloat16* g = (arr == 0) ? g_kh : g_kl;
                v = *(const uint4*)&g[bh + (size_t)(kv0 + row) * HDIM + ch * 8];
                off = (arr == 0) ? KH_OFF : KL_OFF;
            } else {
                const __nv_bfloat16* g = (arr == 2) ? g_vh : g_vl;
                v = *(const uint4*)&g[bh + (size_t)row * SEQ + kv0 + ch * 8];
                off = (arr == 2) ? VH_OFF : VL_OFF;
            }
            *(uint4*)(sm + off + row * SROW + ch * 16) = v;
        }
        __syncthreads();

        if (kv0 <= warp_rmax) {
            // ---- S = Q K^T (bf16x3) ----
            float sc[8][4];
            #pragma unroll
            for (int i = 0; i < 8; i++)
                #pragma unroll
                for (int j = 0; j < 4; j++) sc[i][j] = 0.f;

            #pragma unroll
            for (int ks = 0; ks < 4; ks++) {
                uint32_t qh[4], ql[4];
                ldsm4(qh, q_lane + ks * 32);
                ldsm4(ql, q_lane + ks * 32 + (QL_OFF - QH_OFF));
                #pragma unroll
                for (int kb = 0; kb < 4; kb++) {
                    uint32_t kh[4], kl[4];
                    const uint32_t kaddr = sbase + KH_OFF + (kb * 16 + b_row) * SROW +
                                           ks * 32 + b_kbit * 16;
                    ldsm4(kh, kaddr);
                    ldsm4(kl, kaddr + (KL_OFF - KH_OFF));
                    mma_bf16(sc[2 * kb],     qh, kh[0], kh[1]);
                    mma_bf16(sc[2 * kb],     qh, kl[0], kl[1]);
                    mma_bf16(sc[2 * kb],     ql, kh[0], kh[1]);
                    mma_bf16(sc[2 * kb + 1], qh, kh[2], kh[3]);
                    mma_bf16(sc[2 * kb + 1], qh, kl[2], kl[3]);
                    mma_bf16(sc[2 * kb + 1], ql, kh[2], kh[3]);
                }
            }

            // ---- causal mask ----
            if (kv0 + 63 > warp_rmin) {
                #pragma unroll
                for (int nj = 0; nj < 8; nj++) {
                    const int col = kv0 + nj * 8 + 2 * (lane & 3);
                    if (col     > row_lo)     sc[nj][0] = NEGBIG;
                    if (col + 1 > row_lo)     sc[nj][1] = NEGBIG;
                    if (col     > row_lo + 8) sc[nj][2] = NEGBIG;
                    if (col + 1 > row_lo + 8) sc[nj][3] = NEGBIG;
                }
            }

            // ---- row max (quad reduce) ----
            float mx0 = NEGBIG, mx1 = NEGBIG;
            #pragma unroll
            for (int nj = 0; nj < 8; nj++) {
                mx0 = fmaxf(mx0, fmaxf(sc[nj][0], sc[nj][1]));
                mx1 = fmaxf(mx1, fmaxf(sc[nj][2], sc[nj][3]));
            }
            mx0 = fmaxf(mx0, __shfl_xor_sync(0xffffffffu, mx0, 1));
            mx0 = fmaxf(mx0, __shfl_xor_sync(0xffffffffu, mx0, 2));
            mx1 = fmaxf(mx1, __shfl_xor_sync(0xffffffffu, mx1, 1));
            mx1 = fmaxf(mx1, __shfl_xor_sync(0xffffffffu, mx1, 2));

            const float mn0 = fmaxf(m_lo, mx0);
            const float mn1 = fmaxf(m_hi, mx1);
            const float al0 = ex2(m_lo - mn0);
            const float al1 = ex2(m_hi - mn1);
            m_lo = mn0; m_hi = mn1;

            #pragma unroll
            for (int dt = 0; dt < 8; dt++) {
                o[dt][0] *= al0; o[dt][1] *= al0;
                o[dt][2] *= al1; o[dt][3] *= al1;
            }
            l_lo *= al0; l_hi *= al1;

            // ---- p = exp2(s-m), pack hi/lo, PV MMAs (V smem is [d][kv]) ----
            #pragma unroll
            for (int ks = 0; ks < 4; ks++) {
                uint32_t pah[4], pal[4];
                float s0 = 0.f, s1 = 0.f;
                #pragma unroll
                for (int half = 0; half < 2; half++) {
                    const int nj = 2 * ks + half;
                    float p0 = ex2(sc[nj][0] - mn0);
                    float p1 = ex2(sc[nj][1] - mn0);
                    float p2 = ex2(sc[nj][2] - mn1);
                    float p3 = ex2(sc[nj][3] - mn1);
                    s0 += p0 + p1; s1 += p2 + p3;
                    packsplit2(p0, p1, pah[half * 2],     pal[half * 2]);
                    packsplit2(p2, p3, pah[half * 2 + 1], pal[half * 2 + 1]);
                }
                l_lo += s0; l_hi += s1;

                #pragma unroll
                for (int db = 0; db < 4; db++) {
                    uint32_t vh[4], vl[4];
                    const uint32_t vaddr = sbase + VH_OFF + (db * 16 + b_row) * SROW +
                                           ks * 32 + b_kbit * 16;
                    ldsm4(vh, vaddr);
                    ldsm4(vl, vaddr + (VL_OFF - VH_OFF));
                    mma_bf16(o[2 * db],     pah, vh[0], vh[1]);
                    mma_bf16(o[2 * db],     pal, vh[0], vh[1]);
                    mma_bf16(o[2 * db],     pah, vl[0], vl[1]);
                    mma_bf16(o[2 * db + 1], pah, vh[2], vh[3]);
                    mma_bf16(o[2 * db + 1], pal, vh[2], vh[3]);
                    mma_bf16(o[2 * db + 1], pah, vl[2], vl[3]);
                }
            }
        }
    }

    // ---- l is per-thread partial over its columns; quad-reduce for the
    // full row sum (m/alpha already quad-uniform, so this is exact) ----
    l_lo += __shfl_xor_sync(0xffffffffu, l_lo, 1);
    l_lo += __shfl_xor_sync(0xffffffffu, l_lo, 2);
    l_hi += __shfl_xor_sync(0xffffffffu, l_hi, 1);
    l_hi += __shfl_xor_sync(0xffffffffu, l_hi, 2);

    // ---- epilogue: normalize, bf16 hi/lo split into g_ah/g_al ----
    const float inv0 = 1.f / l_lo;
    const float inv1 = 1.f / l_hi;
    #pragma unroll
    for (int dt = 0; dt < 8; dt++) {
        const int c = h * HDIM + dt * 8 + 2 * (lane & 3);
        uint32_t hi, lo;
        packsplit2(o[dt][0] * inv0, o[dt][1] * inv0, hi, lo);
        size_t off = ((size_t)(b * SEQ + row_lo)) * DIM + c;
        *(uint32_t*)&g_ah[off] = hi;
        *(uint32_t*)&g_al[off] = lo;
        packsplit2(o[dt][2] * inv1, o[dt][3] * inv1, hi, lo);
        off = ((size_t)(b * SEQ + row_lo + 8)) * DIM + c;
        *(uint32_t*)&g_ah[off] = hi;
        *(uint32_t*)&g_al[off] = lo;
    }
}

// ============================================================
extern "C" void kernel_launch(void* const* d_in, const int* in_sizes, int n_in,
                              void* d_out, int out_size)
{
    const float* x      = (const float*)d_in[0];
    const float* w_qkv  = (const float*)d_in[1];
    const float* w_proj = (const float*)d_in[2];
    const float* b_proj = (const float*)d_in[3];
    float* out = (float*)d_out;

    // -- preprocess: split x; transpose+split weights --
    {
        __nv_bfloat16 *xh, *xl, *wqh, *wql, *wph, *wpl;
        cudaGetSymbolAddress((void**)&xh,  g_xh);
        cudaGetSymbolAddress((void**)&xl,  g_xl);
        cudaGetSymbolAddress((void**)&wqh, g_wqh);
        cudaGetSymbolAddress((void**)&wql, g_wql);
        cudaGetSymbolAddress((void**)&wph, g_wph);
        cudaGetSymbolAddress((void**)&wpl, g_wpl);

        const int n4 = NTOK * DIM / 4;
        convert_split_kernel<<<(n4 + 511) / 512, 512>>>(x, xh, xl, n4);

        dim3 blk(32, 8);
        transpose_split_kernel<<<dim3(3 * DIM / 32, DIM / 32), blk>>>(
            w_qkv, wqh, wql, DIM, 3 * DIM);
        transpose_split_kernel<<<dim3(DIM / 32, DIM / 32), blk>>>(
            w_proj, wph, wpl, DIM, DIM);
    }

    // -- QKV GEMM (bf16x3 mma.sync, cp.async): M=8192, N=3072 --
    {
        cudaFuncSetAttribute(qkv_gemm_kernel,
                             cudaFuncAttributeMaxDynamicSharedMemorySize, GEMM_SMEM);
        dim3 grid(3 * DIM / 128, NTOK / 128);
        qkv_gemm_kernel<<<grid, 256, GEMM_SMEM>>>();
    }

    // -- attention (tensor-core bf16x3) --
    {
        cudaFuncSetAttribute(attn_kernel,
                             cudaFuncAttributeMaxDynamicSharedMemorySize, ATT_SMEM);
        dim3 grid(SEQ / 128, NHEADS, BATCH);
        attn_kernel<<<grid, 256, ATT_SMEM>>>();
    }

    // -- projection GEMM (bf16x3 mma.sync, cp.async): M=8192, N=1024 --
    {
        cudaFuncSetAttribute(proj_gemm_kernel,
                             cudaFuncAttributeMaxDynamicSharedMemorySize, GEMM_SMEM);
        dim3 grid(DIM / 128, NTOK / 128);
        proj_gemm_kernel<<<grid, 256, GEMM_SMEM>>>(b_proj, out);
    }
}

// round 8
// speedup vs baseline: 3.3264x; 1.0115x over previous
#include <cuda_runtime.h>
#include <cuda_bf16.h>
#include <cstdint>

#define DIM     1024
#define NHEADS  16
#define HDIM    64
#define SEQ     2048
#define BATCH   4
#define NTOK    (BATCH * SEQ)          // 8192
// SCALE * log2(e) folded into Q so softmax uses exp2
#define QSCALE  0.18033688011112042f
#define NEGBIG  -1e9f

// -------- scratch (device globals: allocation-free) --------
__device__ __nv_bfloat16 g_qh[(size_t)BATCH * NHEADS * SEQ * HDIM]; // [B,H,S,D]
__device__ __nv_bfloat16 g_ql[(size_t)BATCH * NHEADS * SEQ * HDIM];
__device__ __nv_bfloat16 g_kh[(size_t)BATCH * NHEADS * SEQ * HDIM];
__device__ __nv_bfloat16 g_kl[(size_t)BATCH * NHEADS * SEQ * HDIM];
__device__ __nv_bfloat16 g_vh[(size_t)BATCH * NHEADS * HDIM * SEQ]; // [B,H,D,S] !
__device__ __nv_bfloat16 g_vl[(size_t)BATCH * NHEADS * HDIM * SEQ];
__device__ __nv_bfloat16 g_xh[(size_t)NTOK * DIM];             // x hi/lo
__device__ __nv_bfloat16 g_xl[(size_t)NTOK * DIM];
__device__ __nv_bfloat16 g_wqh[(size_t)3 * DIM * DIM];         // w_qkv^T [n][k]
__device__ __nv_bfloat16 g_wql[(size_t)3 * DIM * DIM];
__device__ __nv_bfloat16 g_wph[(size_t)DIM * DIM];             // w_proj^T [n][k]
__device__ __nv_bfloat16 g_wpl[(size_t)DIM * DIM];
__device__ __nv_bfloat16 g_ah[(size_t)NTOK * DIM];             // attn out hi/lo
__device__ __nv_bfloat16 g_al[(size_t)NTOK * DIM];

// ============================================================
// helpers
// ============================================================
__device__ __forceinline__ uint32_t smem_to_u32(const void* p) {
    uint32_t a;
    asm("{ .reg .u64 t; cvta.to.shared.u64 t, %1; cvt.u32.u64 %0, t; }"
        : "=r"(a) : "l"(p));
    return a;
}

__device__ __forceinline__ void bf16split(float v, unsigned short& h, unsigned short& l) {
    __nv_bfloat16 hb = __float2bfloat16(v);
    h = __bfloat16_as_ushort(hb);
    l = __bfloat16_as_ushort(__float2bfloat16(v - __bfloat162float(hb)));
}

// pack 2 floats into bf16x2 hi + residual bf16x2 lo ({lo16=x, hi16=y})
__device__ __forceinline__ void packsplit2(float x, float y, uint32_t& hi, uint32_t& lo) {
    uint32_t h;
    asm("cvt.rn.bf16x2.f32 %0, %1, %2;" : "=r"(h) : "f"(y), "f"(x));
    float fx = __uint_as_float(h << 16);
    float fy = __uint_as_float(h & 0xFFFF0000u);
    uint32_t l;
    float rx = x - fx, ry = y - fy;
    asm("cvt.rn.bf16x2.f32 %0, %1, %2;" : "=r"(l) : "f"(ry), "f"(rx));
    hi = h; lo = l;
}

__device__ __forceinline__ float ex2(float x) {
    float y;
    asm("ex2.approx.f32 %0, %1;" : "=f"(y) : "f"(x));
    return y;
}

__device__ __forceinline__ void ldsm4(uint32_t r[4], uint32_t addr) {
    asm volatile("ldmatrix.sync.aligned.m8n8.x4.shared.b16 {%0,%1,%2,%3}, [%4];"
        : "=r"(r[0]), "=r"(r[1]), "=r"(r[2]), "=r"(r[3]) : "r"(addr));
}

__device__ __forceinline__ void mma_bf16(float d[4], const uint32_t a[4],
                                         uint32_t b0, uint32_t b1) {
    asm volatile(
        "mma.sync.aligned.m16n8k16.row.col.f32.bf16.bf16.f32 "
        "{%0,%1,%2,%3}, {%4,%5,%6,%7}, {%8,%9}, {%0,%1,%2,%3};"
        : "+f"(d[0]), "+f"(d[1]), "+f"(d[2]), "+f"(d[3])
        : "r"(a[0]), "r"(a[1]), "r"(a[2]), "r"(a[3]), "r"(b0), "r"(b1));
}

#define CP_ASYNC16(dst, src) \
    asm volatile("cp.async.cg.shared.global [%0], [%1], 16;" \
        :: "r"(dst), "l"(src) : "memory")
#define CP_COMMIT() asm volatile("cp.async.commit_group;" ::: "memory")
#define CP_WAIT(n)  asm volatile("cp.async.wait_group %0;" :: "n"(n) : "memory")

// ============================================================
// Preprocess kernels
// ============================================================
__global__ void convert_split_kernel(const float* __restrict__ in,
                                     __nv_bfloat16* __restrict__ hi,
                                     __nv_bfloat16* __restrict__ lo, int n4)
{
    const int i = blockIdx.x * blockDim.x + threadIdx.x;
    if (i >= n4) return;
    float4 v = ((const float4*)in)[i];
    unsigned short h[4], l[4];
    bf16split(v.x, h[0], l[0]); bf16split(v.y, h[1], l[1]);
    bf16split(v.z, h[2], l[2]); bf16split(v.w, h[3], l[3]);
    ((uint2*)hi)[i] = make_uint2((uint32_t)h[0] | ((uint32_t)h[1] << 16),
                                 (uint32_t)h[2] | ((uint32_t)h[3] << 16));
    ((uint2*)lo)[i] = make_uint2((uint32_t)l[0] | ((uint32_t)l[1] << 16),
                                 (uint32_t)l[2] | ((uint32_t)l[3] << 16));
}

// in [K][N] fp32 -> out hi/lo [N][K] bf16
__global__ void transpose_split_kernel(const float* __restrict__ in,
                                       __nv_bfloat16* __restrict__ hiT,
                                       __nv_bfloat16* __restrict__ loT,
                                       int K, int N)
{
    __shared__ float t[32][33];
    const int tx = threadIdx.x, ty = threadIdx.y;
    const int k0 = blockIdx.y * 32, n0 = blockIdx.x * 32;
    #pragma unroll
    for (int j = 0; j < 4; j++)
        t[ty + j * 8][tx] = in[(size_t)(k0 + ty + j * 8) * N + n0 + tx];
    __syncthreads();
    #pragma unroll
    for (int j = 0; j < 4; j++) {
        const int nn = n0 + ty + j * 8;
        const int kk = k0 + tx;
        unsigned short h, l;
        bf16split(t[tx][ty + j * 8], h, l);
        hiT[(size_t)nn * K + kk] = __ushort_as_bfloat16(h);
        loT[(size_t)nn * K + kk] = __ushort_as_bfloat16(l);
    }
}

// ============================================================
// bf16x3 mma.sync GEMM: CTA 128x128, 256 threads (8 warps, 64x32 each),
// K=1024 in 32 chunks of 32, cp.async double-buffered smem, 80B rows,
// 2 CTAs/SM.  (unchanged from round 7)
// ============================================================
#define TILE_BYTES 10240            // 128 rows * 80 B
#define BUF_BYTES  (4 * TILE_BYTES) // Ah, Al, Bh, Bl
#define GEMM_SMEM  (2 * BUF_BYTES)  // 81920
#define NCHUNK     32

__device__ __forceinline__ void gemm_issue_chunk(
    const __nv_bfloat16* const gb[4], uint32_t dstbuf, int tid, int c)
{
    #pragma unroll
    for (int i = 0; i < 8; i++) {
        const int s    = tid + i * 256;
        const int tile = s >> 9;          // 512 segments per tile
        const int t2   = s & 511;
        const int row  = t2 >> 2;
        const int kg   = t2 & 3;
        const __nv_bfloat16* src = gb[tile] + (size_t)row * DIM + c * 32 + kg * 8;
        const uint32_t dst = dstbuf + tile * TILE_BYTES + row * 80 + kg * 16;
        CP_ASYNC16(dst, src);
    }
    CP_COMMIT();
}

__device__ __forceinline__ void gemm_mainloop(
    const __nv_bfloat16* __restrict__ Ah, const __nv_bfloat16* __restrict__ Al,
    const __nv_bfloat16* __restrict__ Bh, const __nv_bfloat16* __restrict__ Bl,
    float acc[4][4][4], char* smem)
{
    const uint32_t smem_base = smem_to_u32(smem);
    const int tid  = threadIdx.x;
    const int lane = tid & 31;
    const int wid  = tid >> 5;        // 0..7
    const int wr   = wid >> 2;        // 0..1 -> 64 rows each
    const int wc   = wid & 3;         // 0..3 -> 32 cols each
    const int m0   = blockIdx.y * 128;
    const int n0   = blockIdx.x * 128;

    const __nv_bfloat16* gb[4] = {
        Ah + (size_t)m0 * DIM, Al + (size_t)m0 * DIM,
        Bh + (size_t)n0 * DIM, Bl + (size_t)n0 * DIM };

    const int arow = (lane & 7) + ((lane >> 3) & 1) * 8;
    const int acol = ((lane >> 4) & 1) * 16;
    const int brow = (lane & 7) + ((lane >> 4) & 1) * 8;
    const int bcol = ((lane >> 3) & 1) * 16;

    const uint32_t a_lane = (uint32_t)((wr * 64 + arow) * 80 + acol);
    const uint32_t b_lane = (uint32_t)(2 * TILE_BYTES + (wc * 32 + brow) * 80 + bcol);

    gemm_issue_chunk(gb, smem_base, tid, 0);

    for (int c = 0; c < NCHUNK; c++) {
        const uint32_t buf = smem_base + (uint32_t)(c & 1) * BUF_BYTES;

        if (c + 1 < NCHUNK) {
            gemm_issue_chunk(gb, smem_base + (uint32_t)((c + 1) & 1) * BUF_BYTES,
                             tid, c + 1);
            CP_WAIT(1);
        } else {
            CP_WAIT(0);
        }
        __syncthreads();

        #pragma unroll
        for (int ks = 0; ks < 2; ks++) {
            uint32_t bh2[2][4], bl2[2][4];
            #pragma unroll
            for (int nt = 0; nt < 2; nt++) {
                const uint32_t baddr = buf + b_lane + nt * 16 * 80 + ks * 32;
                ldsm4(bh2[nt], baddr);
                ldsm4(bl2[nt], baddr + TILE_BYTES);
            }
            #pragma unroll
            for (int mt = 0; mt < 4; mt++) {
                uint32_t ah[4], al[4];
                const uint32_t aaddr = buf + a_lane + mt * 16 * 80 + ks * 32;
                ldsm4(ah, aaddr);
                ldsm4(al, aaddr + TILE_BYTES);
                #pragma unroll
                for (int nj = 0; nj < 4; nj++) {
                    const uint32_t b0h = bh2[nj >> 1][(nj & 1) * 2];
                    const uint32_t b1h = bh2[nj >> 1][(nj & 1) * 2 + 1];
                    const uint32_t b0l = bl2[nj >> 1][(nj & 1) * 2];
                    const uint32_t b1l = bl2[nj >> 1][(nj & 1) * 2 + 1];
                    mma_bf16(acc[mt][nj], ah, b0h, b1h);
                    mma_bf16(acc[mt][nj], ah, b0l, b1l);
                    mma_bf16(acc[mt][nj], al, b0h, b1h);
                }
            }
        }
        __syncthreads();   // all warps done reading buf before it is refilled
    }
}

// ============================================================
// Kernel 1: qkv GEMM -> Q/K bf16 hi/lo [B,H,S,D] (Q pre-scaled),
//           V bf16 hi/lo TRANSPOSED [B,H,D,S].
// ============================================================
__global__ void __launch_bounds__(256, 2)
qkv_gemm_kernel()
{
    extern __shared__ __align__(16) char smem[];
    float acc[4][4][4] = {};
    gemm_mainloop(g_xh, g_xl, g_wqh, g_wql, acc, smem);

    const int lane = threadIdx.x & 31;
    const int wid  = threadIdx.x >> 5;
    const int wr   = wid >> 2, wc = wid & 3;
    const int m_base = blockIdx.y * 128 + wr * 64;
    const int n_base = blockIdx.x * 128 + wc * 32;

    #pragma unroll
    for (int mt = 0; mt < 4; mt++) {
        #pragma unroll
        for (int nj = 0; nj < 4; nj++) {
            const int n = n_base + nj * 8 + (lane & 3) * 2;
            const int three = n >> 10;
            const int h = (n >> 6) & 15;
            const int d = n & 63;
            #pragma unroll
            for (int rs = 0; rs < 2; rs++) {
                const int m = m_base + mt * 16 + (lane >> 2) + rs * 8;
                const int b = m >> 11;
                const int s = m & 2047;
                const float x0 = acc[mt][nj][rs * 2];
                const float x1 = acc[mt][nj][rs * 2 + 1];
                if (three == 2) {
                    unsigned short h0, l0, h1, l1;
                    bf16split(x0, h0, l0);
                    bf16split(x1, h1, l1);
                    const size_t tb = ((size_t)(b * NHEADS + h)) * HDIM * SEQ;
                    g_vh[tb + (size_t)d * SEQ + s]       = __ushort_as_bfloat16(h0);
                    g_vl[tb + (size_t)d * SEQ + s]       = __ushort_as_bfloat16(l0);
                    g_vh[tb + (size_t)(d + 1) * SEQ + s] = __ushort_as_bfloat16(h1);
                    g_vl[tb + (size_t)(d + 1) * SEQ + s] = __ushort_as_bfloat16(l1);
                } else {
                    __nv_bfloat16* dsth = (three == 0) ? g_qh : g_kh;
                    __nv_bfloat16* dstl = (three == 0) ? g_ql : g_kl;
                    const float sc = (three == 0) ? QSCALE : 1.0f;
                    uint32_t hi, lo;
                    packsplit2(x0 * sc, x1 * sc, hi, lo);
                    const size_t idx = (((size_t)(b * NHEADS + h)) * SEQ + s) * HDIM + d;
                    *(uint32_t*)&dsth[idx] = hi;
                    *(uint32_t*)&dstl[idx] = lo;
                }
            }
        }
    }
}

// ============================================================
// Kernel 3: out = attn @ w_proj + bias
// ============================================================
__global__ void __launch_bounds__(256, 2)
proj_gemm_kernel(const float* __restrict__ bias, float* __restrict__ out)
{
    extern __shared__ __align__(16) char smem[];
    float acc[4][4][4] = {};
    gemm_mainloop(g_ah, g_al, g_wph, g_wpl, acc, smem);

    const int lane = threadIdx.x & 31;
    const int wid  = threadIdx.x >> 5;
    const int wr   = wid >> 2, wc = wid & 3;
    const int m_base = blockIdx.y * 128 + wr * 64;
    const int n_base = blockIdx.x * 128 + wc * 32;

    #pragma unroll
    for (int mt = 0; mt < 4; mt++) {
        #pragma unroll
        for (int nj = 0; nj < 4; nj++) {
            const int n = n_base + nj * 8 + (lane & 3) * 2;
            const float2 bv = *(const float2*)&bias[n];
            #pragma unroll
            for (int rs = 0; rs < 2; rs++) {
                const int m = m_base + mt * 16 + (lane >> 2) + rs * 8;
                float2 v = make_float2(acc[mt][nj][rs * 2] + bv.x,
                                       acc[mt][nj][rs * 2 + 1] + bv.y);
                *(float2*)&out[(size_t)m * DIM + n] = v;
            }
        }
    }
}

// ============================================================
// Kernel 2: tensor-core causal flash attention, warp tile M=32.
// CTA = 128 q-rows, kv tile 64, 4 warps (32 q-rows each), bf16x3 MMAs.
// Halves per-CTA K/V ldmatrix traffic vs M=16 (B-operand amortization).
// grid (16, 16, 4), 128 threads, 2 CTAs/SM.
// ============================================================
#define SROW    144                 // smem row stride (64 bf16 = 128B + 16 pad)
#define QH_OFF  0
#define QL_OFF  (128 * SROW)        // 18432
#define KH_OFF  (2 * 128 * SROW)    // 36864
#define KL_OFF  (KH_OFF + 64 * SROW)
#define VH_OFF  (KL_OFF + 64 * SROW)
#define VL_OFF  (VH_OFF + 64 * SROW)
#define ATT_SMEM (VL_OFF + 64 * SROW)   // 73728

__global__ void __launch_bounds__(128, 2) attn_kernel()
{
    extern __shared__ __align__(16) char sm[];
    const uint32_t sbase = smem_to_u32(sm);

    const int tid  = threadIdx.x;
    const int lane = tid & 31;
    const int w    = tid >> 5;                     // 0..3
    const int qt   = gridDim.x - 1 - blockIdx.x;   // big tiles first
    const int h    = blockIdx.y;
    const int b    = blockIdx.z;
    const int q0   = qt * 128;
    const size_t bh = ((size_t)(b * NHEADS + h)) * SEQ * HDIM;

    // ---- load Q hi/lo tile (2048 uint4 over 128 threads) ----
    #pragma unroll
    for (int j = 0; j < 16; j++) {
        const int i = tid + j * 128;          // 0..2047
        const int arr = i >> 10;              // 0 hi, 1 lo
        const int t   = i & 1023;
        const int row = t >> 3, ch = t & 7;
        const __nv_bfloat16* g = arr ? g_ql : g_qh;
        uint4 v = *(const uint4*)&g[bh + (size_t)(q0 + row) * HDIM + ch * 8];
        *(uint4*)(sm + (arr ? QL_OFF : QH_OFF) + row * SROW + ch * 16) = v;
    }

    // lane fragment addressing
    const int a_row  = (lane & 7) + ((lane >> 3) & 1) * 8;
    const int a_kbit = (lane >> 4) & 1;
    // per-mt Q fragment base (mt = 0,1 -> rows w*32+mt*16)
    uint32_t q_lane[2];
    #pragma unroll
    for (int mt = 0; mt < 2; mt++)
        q_lane[mt] = sbase + QH_OFF + (w * 32 + mt * 16 + a_row) * SROW + a_kbit * 16;
    const int b_row  = (lane & 7) + ((lane >> 4) & 1) * 8;   // B-operand row (n)
    const int b_kbit = (lane >> 3) & 1;                       // +8 k

    int rl[2];                                   // per-mt low row (lanes>>2)
    rl[0] = q0 + w * 32 + (lane >> 2);
    rl[1] = rl[0] + 16;
    const int warp_rmin = q0 + w * 32;
    const int warp_rmax = warp_rmin + 31;
    const int nkv = 2 * qt + 2;

    float o[2][8][4];
    #pragma unroll
    for (int mt = 0; mt < 2; mt++)
        #pragma unroll
        for (int i = 0; i < 8; i++)
            #pragma unroll
            for (int j = 0; j < 4; j++) o[mt][i][j] = 0.f;
    float m_lo[2] = {NEGBIG, NEGBIG}, m_hi[2] = {NEGBIG, NEGBIG};
    float l_lo[2] = {0.f, 0.f},       l_hi[2] = {0.f, 0.f};

    for (int kt = 0; kt < nkv; kt++) {
        const int kv0 = kt * 64;
        __syncthreads();
        // ---- load K hi/lo [kv][d] and V^T hi/lo [d][kv] (2048 uint4) ----
        #pragma unroll
        for (int j = 0; j < 16; j++) {
            const int i = tid + j * 128;
            const int arr = i >> 9;           // 0 kh, 1 kl, 2 vh, 3 vl
            const int t   = i & 511;
            const int row = t >> 3, ch = t & 7;
            uint4 v;
            int off;
            if (arr < 2) {
                const __nv_bfloat16* g = (arr == 0) ? g_kh : g_kl;
                v = *(const uint4*)&g[bh + (size_t)(kv0 + row) * HDIM + ch * 8];
                off = (arr == 0) ? KH_OFF : KL_OFF;
            } else {
                const __nv_bfloat16* g = (arr == 2) ? g_vh : g_vl;
                v = *(const uint4*)&g[bh + (size_t)row * SEQ + kv0 + ch * 8];
                off = (arr == 2) ? VH_OFF : VL_OFF;
            }
            *(uint4*)(sm + off + row * SROW + ch * 16) = v;
        }
        __syncthreads();

        if (kv0 <= warp_rmax) {
            // ---- S = Q K^T (bf16x3), two m-subtiles per warp ----
            float sc[2][8][4];
            #pragma unroll
            for (int mt = 0; mt < 2; mt++)
                #pragma unroll
                for (int i = 0; i < 8; i++)
                    #pragma unroll
                    for (int j = 0; j < 4; j++) sc[mt][i][j] = 0.f;

            #pragma unroll
            for (int ks = 0; ks < 4; ks++) {
                uint32_t qh[2][4], ql[2][4];
                #pragma unroll
                for (int mt = 0; mt < 2; mt++) {
                    ldsm4(qh[mt], q_lane[mt] + ks * 32);
                    ldsm4(ql[mt], q_lane[mt] + ks * 32 + (QL_OFF - QH_OFF));
                }
                #pragma unroll
                for (int kb = 0; kb < 4; kb++) {
                    uint32_t kh[4], kl[4];
                    const uint32_t kaddr = sbase + KH_OFF + (kb * 16 + b_row) * SROW +
                                           ks * 32 + b_kbit * 16;
                    ldsm4(kh, kaddr);
                    ldsm4(kl, kaddr + (KL_OFF - KH_OFF));
                    #pragma unroll
                    for (int mt = 0; mt < 2; mt++) {
                        mma_bf16(sc[mt][2 * kb],     qh[mt], kh[0], kh[1]);
                        mma_bf16(sc[mt][2 * kb],     qh[mt], kl[0], kl[1]);
                        mma_bf16(sc[mt][2 * kb],     ql[mt], kh[0], kh[1]);
                        mma_bf16(sc[mt][2 * kb + 1], qh[mt], kh[2], kh[3]);
                        mma_bf16(sc[mt][2 * kb + 1], qh[mt], kl[2], kl[3]);
                        mma_bf16(sc[mt][2 * kb + 1], ql[mt], kh[2], kh[3]);
                    }
                }
            }

            // ---- causal mask ----
            if (kv0 + 63 > warp_rmin) {
                #pragma unroll
                for (int mt = 0; mt < 2; mt++)
                    #pragma unroll
                    for (int nj = 0; nj < 8; nj++) {
                        const int col = kv0 + nj * 8 + 2 * (lane & 3);
                        if (col     > rl[mt])     sc[mt][nj][0] = NEGBIG;
                        if (col + 1 > rl[mt])     sc[mt][nj][1] = NEGBIG;
                        if (col     > rl[mt] + 8) sc[mt][nj][2] = NEGBIG;
                        if (col + 1 > rl[mt] + 8) sc[mt][nj][3] = NEGBIG;
                    }
            }

            // ---- row max (quad reduce), rescale o/l ----
            float mn0[2], mn1[2];
            #pragma unroll
            for (int mt = 0; mt < 2; mt++) {
                float mx0 = NEGBIG, mx1 = NEGBIG;
                #pragma unroll
                for (int nj = 0; nj < 8; nj++) {
                    mx0 = fmaxf(mx0, fmaxf(sc[mt][nj][0], sc[mt][nj][1]));
                    mx1 = fmaxf(mx1, fmaxf(sc[mt][nj][2], sc[mt][nj][3]));
                }
                mx0 = fmaxf(mx0, __shfl_xor_sync(0xffffffffu, mx0, 1));
                mx0 = fmaxf(mx0, __shfl_xor_sync(0xffffffffu, mx0, 2));
                mx1 = fmaxf(mx1, __shfl_xor_sync(0xffffffffu, mx1, 1));
                mx1 = fmaxf(mx1, __shfl_xor_sync(0xffffffffu, mx1, 2));

                mn0[mt] = fmaxf(m_lo[mt], mx0);
                mn1[mt] = fmaxf(m_hi[mt], mx1);
                const float al0 = ex2(m_lo[mt] - mn0[mt]);
                const float al1 = ex2(m_hi[mt] - mn1[mt]);
                m_lo[mt] = mn0[mt]; m_hi[mt] = mn1[mt];

                #pragma unroll
                for (int dt = 0; dt < 8; dt++) {
                    o[mt][dt][0] *= al0; o[mt][dt][1] *= al0;
                    o[mt][dt][2] *= al1; o[mt][dt][3] *= al1;
                }
                l_lo[mt] *= al0; l_hi[mt] *= al1;
            }

            // ---- p = exp2(s-m), pack hi/lo, PV MMAs (V smem is [d][kv]) ----
            #pragma unroll
            for (int ks = 0; ks < 4; ks++) {
                uint32_t pah[2][4], pal[2][4];
                #pragma unroll
                for (int mt = 0; mt < 2; mt++) {
                    float s0 = 0.f, s1 = 0.f;
                    #pragma unroll
                    for (int half = 0; half < 2; half++) {
                        const int nj = 2 * ks + half;
                        float p0 = ex2(sc[mt][nj][0] - mn0[mt]);
                        float p1 = ex2(sc[mt][nj][1] - mn0[mt]);
                        float p2 = ex2(sc[mt][nj][2] - mn1[mt]);
                        float p3 = ex2(sc[mt][nj][3] - mn1[mt]);
                        s0 += p0 + p1; s1 += p2 + p3;
                        packsplit2(p0, p1, pah[mt][half * 2],     pal[mt][half * 2]);
                        packsplit2(p2, p3, pah[mt][half * 2 + 1], pal[mt][half * 2 + 1]);
                    }
                    l_lo[mt] += s0; l_hi[mt] += s1;
                }

                #pragma unroll
                for (int db = 0; db < 4; db++) {
                    uint32_t vh[4], vl[4];
                    const uint32_t vaddr = sbase + VH_OFF + (db * 16 + b_row) * SROW +
                                           ks * 32 + b_kbit * 16;
                    ldsm4(vh, vaddr);
                    ldsm4(vl, vaddr + (VL_OFF - VH_OFF));
                    #pragma unroll
                    for (int mt = 0; mt < 2; mt++) {
                        mma_bf16(o[mt][2 * db],     pah[mt], vh[0], vh[1]);
                        mma_bf16(o[mt][2 * db],     pal[mt], vh[0], vh[1]);
                        mma_bf16(o[mt][2 * db],     pah[mt], vl[0], vl[1]);
                        mma_bf16(o[mt][2 * db + 1], pah[mt], vh[2], vh[3]);
                        mma_bf16(o[mt][2 * db + 1], pal[mt], vh[2], vh[3]);
                        mma_bf16(o[mt][2 * db + 1], pah[mt], vl[2], vl[3]);
                    }
                }
            }
        }
    }

    // ---- l is per-thread partial over its columns; quad-reduce for the
    // full row sum (m/alpha already quad-uniform, so this is exact) ----
    #pragma unroll
    for (int mt = 0; mt < 2; mt++) {
        l_lo[mt] += __shfl_xor_sync(0xffffffffu, l_lo[mt], 1);
        l_lo[mt] += __shfl_xor_sync(0xffffffffu, l_lo[mt], 2);
        l_hi[mt] += __shfl_xor_sync(0xffffffffu, l_hi[mt], 1);
        l_hi[mt] += __shfl_xor_sync(0xffffffffu, l_hi[mt], 2);
    }

    // ---- epilogue: normalize, bf16 hi/lo split into g_ah/g_al ----
    #pragma unroll
    for (int mt = 0; mt < 2; mt++) {
        const float inv0 = 1.f / l_lo[mt];
        const float inv1 = 1.f / l_hi[mt];
        #pragma unroll
        for (int dt = 0; dt < 8; dt++) {
            const int c = h * HDIM + dt * 8 + 2 * (lane & 3);
            uint32_t hi, lo;
            packsplit2(o[mt][dt][0] * inv0, o[mt][dt][1] * inv0, hi, lo);
            size_t off = ((size_t)(b * SEQ + rl[mt])) * DIM + c;
            *(uint32_t*)&g_ah[off] = hi;
            *(uint32_t*)&g_al[off] = lo;
            packsplit2(o[mt][dt][2] * inv1, o[mt][dt][3] * inv1, hi, lo);
            off = ((size_t)(b * SEQ + rl[mt] + 8)) * DIM + c;
            *(uint32_t*)&g_ah[off] = hi;
            *(uint32_t*)&g_al[off] = lo;
        }
    }
}

// ============================================================
extern "C" void kernel_launch(void* const* d_in, const int* in_sizes, int n_in,
                              void* d_out, int out_size)
{
    const float* x      = (const float*)d_in[0];
    const float* w_qkv  = (const float*)d_in[1];
    const float* w_proj = (const float*)d_in[2];
    const float* b_proj = (const float*)d_in[3];
    float* out = (float*)d_out;

    // -- preprocess: split x; transpose+split weights --
    {
        __nv_bfloat16 *xh, *xl, *wqh, *wql, *wph, *wpl;
        cudaGetSymbolAddress((void**)&xh,  g_xh);
        cudaGetSymbolAddress((void**)&xl,  g_xl);
        cudaGetSymbolAddress((void**)&wqh, g_wqh);
        cudaGetSymbolAddress((void**)&wql, g_wql);
        cudaGetSymbolAddress((void**)&wph, g_wph);
        cudaGetSymbolAddress((void**)&wpl, g_wpl);

        const int n4 = NTOK * DIM / 4;
        convert_split_kernel<<<(n4 + 511) / 512, 512>>>(x, xh, xl, n4);

        dim3 blk(32, 8);
        transpose_split_kernel<<<dim3(3 * DIM / 32, DIM / 32), blk>>>(
            w_qkv, wqh, wql, DIM, 3 * DIM);
        transpose_split_kernel<<<dim3(DIM / 32, DIM / 32), blk>>>(
            w_proj, wph, wpl, DIM, DIM);
    }

    // -- QKV GEMM (bf16x3 mma.sync, cp.async): M=8192, N=3072 --
    {
        cudaFuncSetAttribute(qkv_gemm_kernel,
                             cudaFuncAttributeMaxDynamicSharedMemorySize, GEMM_SMEM);
        dim3 grid(3 * DIM / 128, NTOK / 128);
        qkv_gemm_kernel<<<grid, 256, GEMM_SMEM>>>();
    }

    // -- attention (tensor-core bf16x3, warp M=32) --
    {
        cudaFuncSetAttribute(attn_kernel,
                             cudaFuncAttributeMaxDynamicSharedMemorySize, ATT_SMEM);
        dim3 grid(SEQ / 128, NHEADS, BATCH);
        attn_kernel<<<grid, 128, ATT_SMEM>>>();
    }

    // -- projection GEMM (bf16x3 mma.sync, cp.async): M=8192, N=1024 --
    {
        cudaFuncSetAttribute(proj_gemm_kernel,
                             cudaFuncAttributeMaxDynamicSharedMemorySize, GEMM_SMEM);
        dim3 grid(DIM / 128, NTOK / 128);
        proj_gemm_kernel<<<grid, 256, GEMM_SMEM>>>(b_proj, out);
    }
}

// round 9
// speedup vs baseline: 3.3301x; 1.0011x over previous
#include <cuda_runtime.h>
#include <cuda_bf16.h>
#include <cstdint>

#define DIM     1024
#define NHEADS  16
#define HDIM    64
#define SEQ     2048
#define BATCH   4
#define NTOK    (BATCH * SEQ)          // 8192
// SCALE * log2(e) folded into Q so softmax uses exp2
#define QSCALE  0.18033688011112042f
#define NEGBIG  -1e9f

// -------- scratch (device globals: allocation-free) --------
__device__ __nv_bfloat16 g_qh[(size_t)BATCH * NHEADS * SEQ * HDIM]; // [B,H,S,D]
__device__ __nv_bfloat16 g_ql[(size_t)BATCH * NHEADS * SEQ * HDIM];
__device__ __nv_bfloat16 g_kh[(size_t)BATCH * NHEADS * SEQ * HDIM];
__device__ __nv_bfloat16 g_kl[(size_t)BATCH * NHEADS * SEQ * HDIM];
__device__ __nv_bfloat16 g_vh[(size_t)BATCH * NHEADS * HDIM * SEQ]; // [B,H,D,S] !
__device__ __nv_bfloat16 g_vl[(size_t)BATCH * NHEADS * HDIM * SEQ];
__device__ __nv_bfloat16 g_xh[(size_t)NTOK * DIM];             // x hi/lo
__device__ __nv_bfloat16 g_xl[(size_t)NTOK * DIM];
__device__ __nv_bfloat16 g_wqh[(size_t)3 * DIM * DIM];         // w_qkv^T [n][k]
__device__ __nv_bfloat16 g_wql[(size_t)3 * DIM * DIM];
__device__ __nv_bfloat16 g_wph[(size_t)DIM * DIM];             // w_proj^T [n][k]
__device__ __nv_bfloat16 g_wpl[(size_t)DIM * DIM];
__device__ __nv_bfloat16 g_ah[(size_t)NTOK * DIM];             // attn out hi/lo
__device__ __nv_bfloat16 g_al[(size_t)NTOK * DIM];

// ============================================================
// helpers
// ============================================================
__device__ __forceinline__ uint32_t smem_to_u32(const void* p) {
    uint32_t a;
    asm("{ .reg .u64 t; cvta.to.shared.u64 t, %1; cvt.u32.u64 %0, t; }"
        : "=r"(a) : "l"(p));
    return a;
}

__device__ __forceinline__ void bf16split(float v, unsigned short& h, unsigned short& l) {
    __nv_bfloat16 hb = __float2bfloat16(v);
    h = __bfloat16_as_ushort(hb);
    l = __bfloat16_as_ushort(__float2bfloat16(v - __bfloat162float(hb)));
}

// pack 2 floats into bf16x2 hi + residual bf16x2 lo ({lo16=x, hi16=y})
__device__ __forceinline__ void packsplit2(float x, float y, uint32_t& hi, uint32_t& lo) {
    uint32_t h;
    asm("cvt.rn.bf16x2.f32 %0, %1, %2;" : "=r"(h) : "f"(y), "f"(x));
    float fx = __uint_as_float(h << 16);
    float fy = __uint_as_float(h & 0xFFFF0000u);
    uint32_t l;
    float rx = x - fx, ry = y - fy;
    asm("cvt.rn.bf16x2.f32 %0, %1, %2;" : "=r"(l) : "f"(ry), "f"(rx));
    hi = h; lo = l;
}

__device__ __forceinline__ float ex2(float x) {
    float y;
    asm("ex2.approx.f32 %0, %1;" : "=f"(y) : "f"(x));
    return y;
}

__device__ __forceinline__ void ldsm4(uint32_t r[4], uint32_t addr) {
    asm volatile("ldmatrix.sync.aligned.m8n8.x4.shared.b16 {%0,%1,%2,%3}, [%4];"
        : "=r"(r[0]), "=r"(r[1]), "=r"(r[2]), "=r"(r[3]) : "r"(addr));
}

__device__ __forceinline__ void mma_bf16(float d[4], const uint32_t a[4],
                                         uint32_t b0, uint32_t b1) {
    asm volatile(
        "mma.sync.aligned.m16n8k16.row.col.f32.bf16.bf16.f32 "
        "{%0,%1,%2,%3}, {%4,%5,%6,%7}, {%8,%9}, {%0,%1,%2,%3};"
        : "+f"(d[0]), "+f"(d[1]), "+f"(d[2]), "+f"(d[3])
        : "r"(a[0]), "r"(a[1]), "r"(a[2]), "r"(a[3]), "r"(b0), "r"(b1));
}

#define CP_ASYNC16(dst, src) \
    asm volatile("cp.async.cg.shared.global [%0], [%1], 16;" \
        :: "r"(dst), "l"(src) : "memory")
#define CP_COMMIT() asm volatile("cp.async.commit_group;" ::: "memory")
#define CP_WAIT(n)  asm volatile("cp.async.wait_group %0;" :: "n"(n) : "memory")

// ============================================================
// Preprocess kernels
// ============================================================
__global__ void convert_split_kernel(const float* __restrict__ in,
                                     __nv_bfloat16* __restrict__ hi,
                                     __nv_bfloat16* __restrict__ lo, int n4)
{
    const int i = blockIdx.x * blockDim.x + threadIdx.x;
    if (i >= n4) return;
    float4 v = ((const float4*)in)[i];
    unsigned short h[4], l[4];
    bf16split(v.x, h[0], l[0]); bf16split(v.y, h[1], l[1]);
    bf16split(v.z, h[2], l[2]); bf16split(v.w, h[3], l[3]);
    ((uint2*)hi)[i] = make_uint2((uint32_t)h[0] | ((uint32_t)h[1] << 16),
                                 (uint32_t)h[2] | ((uint32_t)h[3] << 16));
    ((uint2*)lo)[i] = make_uint2((uint32_t)l[0] | ((uint32_t)l[1] << 16),
                                 (uint32_t)l[2] | ((uint32_t)l[3] << 16));
}

// in [K][N] fp32 -> out hi/lo [N][K] bf16
__global__ void transpose_split_kernel(const float* __restrict__ in,
                                       __nv_bfloat16* __restrict__ hiT,
                                       __nv_bfloat16* __restrict__ loT,
                                       int K, int N)
{
    __shared__ float t[32][33];
    const int tx = threadIdx.x, ty = threadIdx.y;
    const int k0 = blockIdx.y * 32, n0 = blockIdx.x * 32;
    #pragma unroll
    for (int j = 0; j < 4; j++)
        t[ty + j * 8][tx] = in[(size_t)(k0 + ty + j * 8) * N + n0 + tx];
    __syncthreads();
    #pragma unroll
    for (int j = 0; j < 4; j++) {
        const int nn = n0 + ty + j * 8;
        const int kk = k0 + tx;
        unsigned short h, l;
        bf16split(t[tx][ty + j * 8], h, l);
        hiT[(size_t)nn * K + kk] = __ushort_as_bfloat16(h);
        loT[(size_t)nn * K + kk] = __ushort_as_bfloat16(l);
    }
}

// ============================================================
// bf16x3 mma.sync GEMM: CTA 128x128, 256 threads (8 warps, 64x32 each),
// K=1024 in 32 chunks of 32, cp.async double-buffered smem, 80B rows,
// 2 CTAs/SM.  (unchanged)
// ============================================================
#define TILE_BYTES 10240            // 128 rows * 80 B
#define BUF_BYTES  (4 * TILE_BYTES) // Ah, Al, Bh, Bl
#define GEMM_SMEM  (2 * BUF_BYTES)  // 81920
#define NCHUNK     32

__device__ __forceinline__ void gemm_issue_chunk(
    const __nv_bfloat16* const gb[4], uint32_t dstbuf, int tid, int c)
{
    #pragma unroll
    for (int i = 0; i < 8; i++) {
        const int s    = tid + i * 256;
        const int tile = s >> 9;          // 512 segments per tile
        const int t2   = s & 511;
        const int row  = t2 >> 2;
        const int kg   = t2 & 3;
        const __nv_bfloat16* src = gb[tile] + (size_t)row * DIM + c * 32 + kg * 8;
        const uint32_t dst = dstbuf + tile * TILE_BYTES + row * 80 + kg * 16;
        CP_ASYNC16(dst, src);
    }
    CP_COMMIT();
}

__device__ __forceinline__ void gemm_mainloop(
    const __nv_bfloat16* __restrict__ Ah, const __nv_bfloat16* __restrict__ Al,
    const __nv_bfloat16* __restrict__ Bh, const __nv_bfloat16* __restrict__ Bl,
    float acc[4][4][4], char* smem)
{
    const uint32_t smem_base = smem_to_u32(smem);
    const int tid  = threadIdx.x;
    const int lane = tid & 31;
    const int wid  = tid >> 5;        // 0..7
    const int wr   = wid >> 2;        // 0..1 -> 64 rows each
    const int wc   = wid & 3;         // 0..3 -> 32 cols each
    const int m0   = blockIdx.y * 128;
    const int n0   = blockIdx.x * 128;

    const __nv_bfloat16* gb[4] = {
        Ah + (size_t)m0 * DIM, Al + (size_t)m0 * DIM,
        Bh + (size_t)n0 * DIM, Bl + (size_t)n0 * DIM };

    const int arow = (lane & 7) + ((lane >> 3) & 1) * 8;
    const int acol = ((lane >> 4) & 1) * 16;
    const int brow = (lane & 7) + ((lane >> 4) & 1) * 8;
    const int bcol = ((lane >> 3) & 1) * 16;

    const uint32_t a_lane = (uint32_t)((wr * 64 + arow) * 80 + acol);
    const uint32_t b_lane = (uint32_t)(2 * TILE_BYTES + (wc * 32 + brow) * 80 + bcol);

    gemm_issue_chunk(gb, smem_base, tid, 0);

    for (int c = 0; c < NCHUNK; c++) {
        const uint32_t buf = smem_base + (uint32_t)(c & 1) * BUF_BYTES;

        if (c + 1 < NCHUNK) {
            gemm_issue_chunk(gb, smem_base + (uint32_t)((c + 1) & 1) * BUF_BYTES,
                             tid, c + 1);
            CP_WAIT(1);
        } else {
            CP_WAIT(0);
        }
        __syncthreads();

        #pragma unroll
        for (int ks = 0; ks < 2; ks++) {
            uint32_t bh2[2][4], bl2[2][4];
            #pragma unroll
            for (int nt = 0; nt < 2; nt++) {
                const uint32_t baddr = buf + b_lane + nt * 16 * 80 + ks * 32;
                ldsm4(bh2[nt], baddr);
                ldsm4(bl2[nt], baddr + TILE_BYTES);
            }
            #pragma unroll
            for (int mt = 0; mt < 4; mt++) {
                uint32_t ah[4], al[4];
                const uint32_t aaddr = buf + a_lane + mt * 16 * 80 + ks * 32;
                ldsm4(ah, aaddr);
                ldsm4(al, aaddr + TILE_BYTES);
                #pragma unroll
                for (int nj = 0; nj < 4; nj++) {
                    const uint32_t b0h = bh2[nj >> 1][(nj & 1) * 2];
                    const uint32_t b1h = bh2[nj >> 1][(nj & 1) * 2 + 1];
                    const uint32_t b0l = bl2[nj >> 1][(nj & 1) * 2];
                    const uint32_t b1l = bl2[nj >> 1][(nj & 1) * 2 + 1];
                    mma_bf16(acc[mt][nj], ah, b0h, b1h);
                    mma_bf16(acc[mt][nj], ah, b0l, b1l);
                    mma_bf16(acc[mt][nj], al, b0h, b1h);
                }
            }
        }
        __syncthreads();   // all warps done reading buf before it is refilled
    }
}

// ============================================================
// Kernel 1: qkv GEMM -> Q/K bf16 hi/lo [B,H,S,D] (Q pre-scaled),
//           V bf16 hi/lo TRANSPOSED [B,H,D,S].
// ============================================================
__global__ void __launch_bounds__(256, 2)
qkv_gemm_kernel()
{
    extern __shared__ __align__(16) char smem[];
    float acc[4][4][4] = {};
    gemm_mainloop(g_xh, g_xl, g_wqh, g_wql, acc, smem);

    const int lane = threadIdx.x & 31;
    const int wid  = threadIdx.x >> 5;
    const int wr   = wid >> 2, wc = wid & 3;
    const int m_base = blockIdx.y * 128 + wr * 64;
    const int n_base = blockIdx.x * 128 + wc * 32;

    #pragma unroll
    for (int mt = 0; mt < 4; mt++) {
        #pragma unroll
        for (int nj = 0; nj < 4; nj++) {
            const int n = n_base + nj * 8 + (lane & 3) * 2;
            const int three = n >> 10;
            const int h = (n >> 6) & 15;
            const int d = n & 63;
            #pragma unroll
            for (int rs = 0; rs < 2; rs++) {
                const int m = m_base + mt * 16 + (lane >> 2) + rs * 8;
                const int b = m >> 11;
                const int s = m & 2047;
                const float x0 = acc[mt][nj][rs * 2];
                const float x1 = acc[mt][nj][rs * 2 + 1];
                if (three == 2) {
                    unsigned short h0, l0, h1, l1;
                    bf16split(x0, h0, l0);
                    bf16split(x1, h1, l1);
                    const size_t tb = ((size_t)(b * NHEADS + h)) * HDIM * SEQ;
                    g_vh[tb + (size_t)d * SEQ + s]       = __ushort_as_bfloat16(h0);
                    g_vl[tb + (size_t)d * SEQ + s]       = __ushort_as_bfloat16(l0);
                    g_vh[tb + (size_t)(d + 1) * SEQ + s] = __ushort_as_bfloat16(h1);
                    g_vl[tb + (size_t)(d + 1) * SEQ + s] = __ushort_as_bfloat16(l1);
                } else {
                    __nv_bfloat16* dsth = (three == 0) ? g_qh : g_kh;
                    __nv_bfloat16* dstl = (three == 0) ? g_ql : g_kl;
                    const float sc = (three == 0) ? QSCALE : 1.0f;
                    uint32_t hi, lo;
                    packsplit2(x0 * sc, x1 * sc, hi, lo);
                    const size_t idx = (((size_t)(b * NHEADS + h)) * SEQ + s) * HDIM + d;
                    *(uint32_t*)&dsth[idx] = hi;
                    *(uint32_t*)&dstl[idx] = lo;
                }
            }
        }
    }
}

// ============================================================
// Kernel 3: out = attn @ w_proj + bias
// ============================================================
__global__ void __launch_bounds__(256, 2)
proj_gemm_kernel(const float* __restrict__ bias, float* __restrict__ out)
{
    extern __shared__ __align__(16) char smem[];
    float acc[4][4][4] = {};
    gemm_mainloop(g_ah, g_al, g_wph, g_wpl, acc, smem);

    const int lane = threadIdx.x & 31;
    const int wid  = threadIdx.x >> 5;
    const int wr   = wid >> 2, wc = wid & 3;
    const int m_base = blockIdx.y * 128 + wr * 64;
    const int n_base = blockIdx.x * 128 + wc * 32;

    #pragma unroll
    for (int mt = 0; mt < 4; mt++) {
        #pragma unroll
        for (int nj = 0; nj < 4; nj++) {
            const int n = n_base + nj * 8 + (lane & 3) * 2;
            const float2 bv = *(const float2*)&bias[n];
            #pragma unroll
            for (int rs = 0; rs < 2; rs++) {
                const int m = m_base + mt * 16 + (lane >> 2) + rs * 8;
                float2 v = make_float2(acc[mt][nj][rs * 2] + bv.x,
                                       acc[mt][nj][rs * 2 + 1] + bv.y);
                *(float2*)&out[(size_t)m * DIM + n] = v;
            }
        }
    }
}

// ============================================================
// Kernel 2: tensor-core causal flash attention, warp tile M=32,
// cp.async DOUBLE-BUFFERED K/V (overlap next-tile load with compute).
// CTA = 128 q-rows, kv tile 64, 4 warps, bf16x3 MMAs, 2 CTAs/SM.
// ============================================================
#define SROW     144                 // smem row stride (64 bf16 = 128B + 16 pad)
#define QH_OFF   0
#define QL_OFF   (128 * SROW)        // 18432
#define KV_BASE  (2 * 128 * SROW)    // 36864
#define T_OFF    (64 * SROW)         // 9216 per tile (kh, kl, vh, vl)
#define KV_STAGE (4 * T_OFF)         // 36864 per stage
#define ATT_SMEM (KV_BASE + 2 * KV_STAGE)   // 110592

__device__ __forceinline__ void attn_issue_kv(uint32_t dstbase, size_t bh,
                                              int kv0, int tid)
{
    #pragma unroll
    for (int j = 0; j < 16; j++) {
        const int i = tid + j * 128;
        const int arr = i >> 9;           // 0 kh, 1 kl, 2 vh, 3 vl
        const int t   = i & 511;
        const int row = t >> 3, ch = t & 7;
        const __nv_bfloat16* src;
        if      (arr == 0) src = &g_kh[bh + (size_t)(kv0 + row) * HDIM + ch * 8];
        else if (arr == 1) src = &g_kl[bh + (size_t)(kv0 + row) * HDIM + ch * 8];
        else if (arr == 2) src = &g_vh[bh + (size_t)row * SEQ + kv0 + ch * 8];
        else               src = &g_vl[bh + (size_t)row * SEQ + kv0 + ch * 8];
        const uint32_t dst = dstbase + arr * T_OFF + row * SROW + ch * 16;
        CP_ASYNC16(dst, src);
    }
    CP_COMMIT();
}

__global__ void __launch_bounds__(128, 2) attn_kernel()
{
    extern __shared__ __align__(16) char sm[];
    const uint32_t sbase = smem_to_u32(sm);

    const int tid  = threadIdx.x;
    const int lane = tid & 31;
    const int w    = tid >> 5;                     // 0..3
    const int qt   = gridDim.x - 1 - blockIdx.x;   // big tiles first
    const int h    = blockIdx.y;
    const int b    = blockIdx.z;
    const int q0   = qt * 128;
    const size_t bh = ((size_t)(b * NHEADS + h)) * SEQ * HDIM;

    const int nkv = 2 * qt + 2;

    // issue first K/V stage before touching Q (maximize overlap)
    attn_issue_kv(sbase + KV_BASE, bh, 0, tid);

    // ---- load Q hi/lo tile (plain; one-time) ----
    #pragma unroll
    for (int j = 0; j < 16; j++) {
        const int i = tid + j * 128;          // 0..2047
        const int arr = i >> 10;              // 0 hi, 1 lo
        const int t   = i & 1023;
        const int row = t >> 3, ch = t & 7;
        const __nv_bfloat16* g = arr ? g_ql : g_qh;
        uint4 v = *(const uint4*)&g[bh + (size_t)(q0 + row) * HDIM + ch * 8];
        *(uint4*)(sm + (arr ? QL_OFF : QH_OFF) + row * SROW + ch * 16) = v;
    }

    // lane fragment addressing
    const int a_row  = (lane & 7) + ((lane >> 3) & 1) * 8;
    const int a_kbit = (lane >> 4) & 1;
    uint32_t q_lane[2];
    #pragma unroll
    for (int mt = 0; mt < 2; mt++)
        q_lane[mt] = sbase + QH_OFF + (w * 32 + mt * 16 + a_row) * SROW + a_kbit * 16;
    const int b_row  = (lane & 7) + ((lane >> 4) & 1) * 8;   // B-operand row (n)
    const int b_kbit = (lane >> 3) & 1;                       // +8 k

    int rl[2];
    rl[0] = q0 + w * 32 + (lane >> 2);
    rl[1] = rl[0] + 16;
    const int warp_rmin = q0 + w * 32;
    const int warp_rmax = warp_rmin + 31;

    float o[2][8][4];
    #pragma unroll
    for (int mt = 0; mt < 2; mt++)
        #pragma unroll
        for (int i = 0; i < 8; i++)
            #pragma unroll
            for (int j = 0; j < 4; j++) o[mt][i][j] = 0.f;
    float m_lo[2] = {NEGBIG, NEGBIG}, m_hi[2] = {NEGBIG, NEGBIG};
    float l_lo[2] = {0.f, 0.f},       l_hi[2] = {0.f, 0.f};

    for (int kt = 0; kt < nkv; kt++) {
        const int kv0 = kt * 64;

        CP_WAIT(0);          // this thread's copies for tile kt complete
        __syncthreads();     // whole tile kt visible; everyone past compute(kt-1)

        // prefetch tile kt+1 into the other stage (overlaps compute below)
        if (kt + 1 < nkv)
            attn_issue_kv(sbase + KV_BASE + (uint32_t)((kt + 1) & 1) * KV_STAGE,
                          bh, kv0 + 64, tid);

        const uint32_t stg = sbase + KV_BASE + (uint32_t)(kt & 1) * KV_STAGE;

        if (kv0 <= warp_rmax) {
            // ---- S = Q K^T (bf16x3), two m-subtiles per warp ----
            float sc[2][8][4];
            #pragma unroll
            for (int mt = 0; mt < 2; mt++)
                #pragma unroll
                for (int i = 0; i < 8; i++)
                    #pragma unroll
                    for (int j = 0; j < 4; j++) sc[mt][i][j] = 0.f;

            #pragma unroll
            for (int ks = 0; ks < 4; ks++) {
                uint32_t qh[2][4], ql[2][4];
                #pragma unroll
                for (int mt = 0; mt < 2; mt++) {
                    ldsm4(qh[mt], q_lane[mt] + ks * 32);
                    ldsm4(ql[mt], q_lane[mt] + ks * 32 + (QL_OFF - QH_OFF));
                }
                #pragma unroll
                for (int kb = 0; kb < 4; kb++) {
                    uint32_t kh[4], kl[4];
                    const uint32_t kaddr = stg + (kb * 16 + b_row) * SROW +
                                           ks * 32 + b_kbit * 16;
                    ldsm4(kh, kaddr);
                    ldsm4(kl, kaddr + T_OFF);
                    #pragma unroll
                    for (int mt = 0; mt < 2; mt++) {
                        mma_bf16(sc[mt][2 * kb],     qh[mt], kh[0], kh[1]);
                        mma_bf16(sc[mt][2 * kb],     qh[mt], kl[0], kl[1]);
                        mma_bf16(sc[mt][2 * kb],     ql[mt], kh[0], kh[1]);
                        mma_bf16(sc[mt][2 * kb + 1], qh[mt], kh[2], kh[3]);
                        mma_bf16(sc[mt][2 * kb + 1], qh[mt], kl[2], kl[3]);
                        mma_bf16(sc[mt][2 * kb + 1], ql[mt], kh[2], kh[3]);
                    }
                }
            }

            // ---- causal mask ----
            if (kv0 + 63 > warp_rmin) {
                #pragma unroll
                for (int mt = 0; mt < 2; mt++)
                    #pragma unroll
                    for (int nj = 0; nj < 8; nj++) {
                        const int col = kv0 + nj * 8 + 2 * (lane & 3);
                        if (col     > rl[mt])     sc[mt][nj][0] = NEGBIG;
                        if (col + 1 > rl[mt])     sc[mt][nj][1] = NEGBIG;
                        if (col     > rl[mt] + 8) sc[mt][nj][2] = NEGBIG;
                        if (col + 1 > rl[mt] + 8) sc[mt][nj][3] = NEGBIG;
                    }
            }

            // ---- row max (quad reduce), rescale o/l ----
            float mn0[2], mn1[2];
            #pragma unroll
            for (int mt = 0; mt < 2; mt++) {
                float mx0 = NEGBIG, mx1 = NEGBIG;
                #pragma unroll
                for (int nj = 0; nj < 8; nj++) {
                    mx0 = fmaxf(mx0, fmaxf(sc[mt][nj][0], sc[mt][nj][1]));
                    mx1 = fmaxf(mx1, fmaxf(sc[mt][nj][2], sc[mt][nj][3]));
                }
                mx0 = fmaxf(mx0, __shfl_xor_sync(0xffffffffu, mx0, 1));
                mx0 = fmaxf(mx0, __shfl_xor_sync(0xffffffffu, mx0, 2));
                mx1 = fmaxf(mx1, __shfl_xor_sync(0xffffffffu, mx1, 1));
                mx1 = fmaxf(mx1, __shfl_xor_sync(0xffffffffu, mx1, 2));

                mn0[mt] = fmaxf(m_lo[mt], mx0);
                mn1[mt] = fmaxf(m_hi[mt], mx1);
                const float al0 = ex2(m_lo[mt] - mn0[mt]);
                const float al1 = ex2(m_hi[mt] - mn1[mt]);
                m_lo[mt] = mn0[mt]; m_hi[mt] = mn1[mt];

                #pragma unroll
                for (int dt = 0; dt < 8; dt++) {
                    o[mt][dt][0] *= al0; o[mt][dt][1] *= al0;
                    o[mt][dt][2] *= al1; o[mt][dt][3] *= al1;
                }
                l_lo[mt] *= al0; l_hi[mt] *= al1;
            }

            // ---- p = exp2(s-m), pack hi/lo, PV MMAs (V smem is [d][kv]) ----
            #pragma unroll
            for (int ks = 0; ks < 4; ks++) {
                uint32_t pah[2][4], pal[2][4];
                #pragma unroll
                for (int mt = 0; mt < 2; mt++) {
                    float s0 = 0.f, s1 = 0.f;
                    #pragma unroll
                    for (int half = 0; half < 2; half++) {
                        const int nj = 2 * ks + half;
                        float p0 = ex2(sc[mt][nj][0] - mn0[mt]);
                        float p1 = ex2(sc[mt][nj][1] - mn0[mt]);
                        float p2 = ex2(sc[mt][nj][2] - mn1[mt]);
                        float p3 = ex2(sc[mt][nj][3] - mn1[mt]);
                        s0 += p0 + p1; s1 += p2 + p3;
                        packsplit2(p0, p1, pah[mt][half * 2],     pal[mt][half * 2]);
                        packsplit2(p2, p3, pah[mt][half * 2 + 1], pal[mt][half * 2 + 1]);
                    }
                    l_lo[mt] += s0; l_hi[mt] += s1;
                }

                #pragma unroll
                for (int db = 0; db < 4; db++) {
                    uint32_t vh[4], vl[4];
                    const uint32_t vaddr = stg + 2 * T_OFF + (db * 16 + b_row) * SROW +
                                           ks * 32 + b_kbit * 16;
                    ldsm4(vh, vaddr);
                    ldsm4(vl, vaddr + T_OFF);
                    #pragma unroll
                    for (int mt = 0; mt < 2; mt++) {
                        mma_bf16(o[mt][2 * db],     pah[mt], vh[0], vh[1]);
                        mma_bf16(o[mt][2 * db],     pal[mt], vh[0], vh[1]);
                        mma_bf16(o[mt][2 * db],     pah[mt], vl[0], vl[1]);
                        mma_bf16(o[mt][2 * db + 1], pah[mt], vh[2], vh[3]);
                        mma_bf16(o[mt][2 * db + 1], pal[mt], vh[2], vh[3]);
                        mma_bf16(o[mt][2 * db + 1], pah[mt], vl[2], vl[3]);
                    }
                }
            }
        }
    }

    // ---- l is per-thread partial over its columns; quad-reduce for the
    // full row sum (m/alpha already quad-uniform, so this is exact) ----
    #pragma unroll
    for (int mt = 0; mt < 2; mt++) {
        l_lo[mt] += __shfl_xor_sync(0xffffffffu, l_lo[mt], 1);
        l_lo[mt] += __shfl_xor_sync(0xffffffffu, l_lo[mt], 2);
        l_hi[mt] += __shfl_xor_sync(0xffffffffu, l_hi[mt], 1);
        l_hi[mt] += __shfl_xor_sync(0xffffffffu, l_hi[mt], 2);
    }

    // ---- epilogue: normalize, bf16 hi/lo split into g_ah/g_al ----
    #pragma unroll
    for (int mt = 0; mt < 2; mt++) {
        const float inv0 = 1.f / l_lo[mt];
        const float inv1 = 1.f / l_hi[mt];
        #pragma unroll
        for (int dt = 0; dt < 8; dt++) {
            const int c = h * HDIM + dt * 8 + 2 * (lane & 3);
            uint32_t hi, lo;
            packsplit2(o[mt][dt][0] * inv0, o[mt][dt][1] * inv0, hi, lo);
            size_t off = ((size_t)(b * SEQ + rl[mt])) * DIM + c;
            *(uint32_t*)&g_ah[off] = hi;
            *(uint32_t*)&g_al[off] = lo;
            packsplit2(o[mt][dt][2] * inv1, o[mt][dt][3] * inv1, hi, lo);
            off = ((size_t)(b * SEQ + rl[mt] + 8)) * DIM + c;
            *(uint32_t*)&g_ah[off] = hi;
            *(uint32_t*)&g_al[off] = lo;
        }
    }
}

// ============================================================
extern "C" void kernel_launch(void* const* d_in, const int* in_sizes, int n_in,
                              void* d_out, int out_size)
{
    const float* x      = (const float*)d_in[0];
    const float* w_qkv  = (const float*)d_in[1];
    const float* w_proj = (const float*)d_in[2];
    const float* b_proj = (const float*)d_in[3];
    float* out = (float*)d_out;

    // -- preprocess: split x; transpose+split weights --
    {
        __nv_bfloat16 *xh, *xl, *wqh, *wql, *wph, *wpl;
        cudaGetSymbolAddress((void**)&xh,  g_xh);
        cudaGetSymbolAddress((void**)&xl,  g_xl);
        cudaGetSymbolAddress((void**)&wqh, g_wqh);
        cudaGetSymbolAddress((void**)&wql, g_wql);
        cudaGetSymbolAddress((void**)&wph, g_wph);
        cudaGetSymbolAddress((void**)&wpl, g_wpl);

        const int n4 = NTOK * DIM / 4;
        convert_split_kernel<<<(n4 + 511) / 512, 512>>>(x, xh, xl, n4);

        dim3 blk(32, 8);
        transpose_split_kernel<<<dim3(3 * DIM / 32, DIM / 32), blk>>>(
            w_qkv, wqh, wql, DIM, 3 * DIM);
        transpose_split_kernel<<<dim3(DIM / 32, DIM / 32), blk>>>(
            w_proj, wph, wpl, DIM, DIM);
    }

    // -- QKV GEMM (bf16x3 mma.sync, cp.async): M=8192, N=3072 --
    {
        cudaFuncSetAttribute(qkv_gemm_kernel,
                             cudaFuncAttributeMaxDynamicSharedMemorySize, GEMM_SMEM);
        dim3 grid(3 * DIM / 128, NTOK / 128);
        qkv_gemm_kernel<<<grid, 256, GEMM_SMEM>>>();
    }

    // -- attention (tensor-core bf16x3, cp.async double-buffered K/V) --
    {
        cudaFuncSetAttribute(attn_kernel,
                             cudaFuncAttributeMaxDynamicSharedMemorySize, ATT_SMEM);
        dim3 grid(SEQ / 128, NHEADS, BATCH);
        attn_kernel<<<grid, 128, ATT_SMEM>>>();
    }

    // -- projection GEMM (bf16x3 mma.sync, cp.async): M=8192, N=1024 --
    {
        cudaFuncSetAttribute(proj_gemm_kernel,
                             cudaFuncAttributeMaxDynamicSharedMemorySize, GEMM_SMEM);
        dim3 grid(DIM / 128, NTOK / 128);
        proj_gemm_kernel<<<grid, 256, GEMM_SMEM>>>(b_proj, out);
    }
}